// round 9
// baseline (speedup 1.0000x reference)
#include <cuda_runtime.h>
#include <cuda_bf16.h>
#include <math.h>
#include <stdint.h>

#define BB   128
#define TT   24
#define EE   512
#define HH   512
#define VV   10000
#define G4   2048
#define BTR  3072
#define OUTROW 250000
#define NPAD 10112          // 79 * 128  (padded vocab rows)

// ---------------- device scratch (no allocations allowed) ----------------
__device__ __nv_bfloat16 g_Xhi [BTR * EE], g_Xlo [BTR * EE];     // embedded captions
__device__ __nv_bfloat16 g_Wihhi[G4 * EE], g_Wihlo[G4 * EE];     // permuted W_ih
__device__ __nv_bfloat16 g_Whhhi[G4 * HH], g_Whhlo[G4 * HH];     // permuted W_hh
__device__ __nv_bfloat16 g_Wouthi[NPAD * HH], g_Woutlo[NPAD * HH];
__device__ __nv_bfloat16 g_Hhi [BTR * HH], g_Hlo [BTR * HH];     // all hidden states
__device__ __nv_bfloat16 g_hAhi[BB * HH], g_hAlo[BB * HH];
__device__ __nv_bfloat16 g_hBhi[BB * HH], g_hBlo[BB * HH];
__device__ float g_c   [BB * HH];
__device__ float g_bias[G4];                                     // permuted b_ih+b_hh
__device__ float g_Xg  [BTR * G4];                               // input gates (permuted cols)

// ---------------- small helpers ----------------
__device__ __forceinline__ float sigf(float x) { return 1.0f / (1.0f + expf(-x)); }

__device__ __forceinline__ void split2(float x, __nv_bfloat16& h, __nv_bfloat16& l) {
    h = __float2bfloat16(x);
    l = __float2bfloat16(x - __bfloat162float(h));
}

__device__ __forceinline__ uint32_t smem_to_u32(const void* p) {
    uint32_t a;
    asm("{ .reg .u64 t; cvta.to.shared.u64 t, %1; cvt.u32.u64 %0, t; }" : "=r"(a) : "l"(p));
    return a;
}

// ---------------- warp-level tensor ops (sm_80+ PTX; legal on plain sm_103) ----
__device__ __forceinline__ void ldsm_x4(uint32_t* r, uint32_t addr) {
    asm volatile("ldmatrix.sync.aligned.m8n8.x4.shared.b16 {%0,%1,%2,%3}, [%4];"
                 : "=r"(r[0]), "=r"(r[1]), "=r"(r[2]), "=r"(r[3]) : "r"(addr));
}

__device__ __forceinline__ void mma_bf16(float* c, const uint32_t* a, const uint32_t* b) {
    asm volatile(
        "mma.sync.aligned.m16n8k16.row.col.f32.bf16.bf16.f32 "
        "{%0,%1,%2,%3}, {%4,%5,%6,%7}, {%8,%9}, {%0,%1,%2,%3};"
        : "+f"(c[0]), "+f"(c[1]), "+f"(c[2]), "+f"(c[3])
        : "r"(a[0]), "r"(a[1]), "r"(a[2]), "r"(a[3]), "r"(b[0]), "r"(b[1]));
}

// ---------------- smem layout ----------------
// Tile = 128 rows x 64 bf16 k, rows padded to 72 elems (144B) -> 18432 B/plane.
// Row stride 144B = 36 words; 36 mod 32 = 4 => 8 consecutive rows hit all 32
// banks with their 4-word ldmatrix segments: conflict-free.
#define TILE_B  (128 * 144)
#define SM_AH   0
#define SM_AL   (1 * TILE_B)
#define SM_BH   (2 * TILE_B)
#define SM_BL   (3 * TILE_B)
#define SMEM_DYN (4 * TILE_B)     // 73728 bytes

// Load one 128x64 bf16 tile (gmem ld = 512) into padded smem rows.
__device__ __forceinline__ void load_tile(char* dst, const __nv_bfloat16* src,
                                          int row0, int k0, int tid) {
#pragma unroll
    for (int i = 0; i < 4; i++) {
        int e  = tid + i * 256;           // 0..1023 groups of 8 bf16
        int r  = e >> 3;                  // 0..127
        int k8 = (e & 7) << 3;            // 0..56
        uint4 v = *(const uint4*)(src + (size_t)(row0 + r) * 512 + k0 + k8);
        *(uint4*)(dst + r * 144 + k8 * 2) = v;
    }
}

// ---------------- shared mainloop ----------------
// acc[mi][ni][4] += A(hi+lo)[128xK] @ B(hi+lo)[128xK]^T  (3-product bf16 emulation)
// Warp grid: 8 warps = 2(m) x 4(n); warp tile 64m x 32n; K = 512, K-tile 64.
__device__ __forceinline__ void gemm_mainloop(char* sm,
        const __nv_bfloat16* Ahi, const __nv_bfloat16* Alo, int arow0,
        const __nv_bfloat16* Bhi, const __nv_bfloat16* Blo, int brow0,
        float acc[4][4][4]) {
    const int tid  = threadIdx.x;
    const int lane = tid & 31;
    const int w    = tid >> 5;
    const int wm   = w & 1;
    const int wn   = w >> 1;
    const uint32_t sb = smem_to_u32(sm);

    const int lrow = lane & 15;
    const int lcol = (lane >> 4) * 16;    // byte offset within 32B k16 chunk

    for (int kt = 0; kt < 8; kt++) {
        int k0 = kt * 64;
        load_tile(sm + SM_AH, Ahi, arow0, k0, tid);
        load_tile(sm + SM_AL, Alo, arow0, k0, tid);
        load_tile(sm + SM_BH, Bhi, brow0, k0, tid);
        load_tile(sm + SM_BL, Blo, brow0, k0, tid);
        __syncthreads();

#pragma unroll
        for (int kc = 0; kc < 4; kc++) {
            uint32_t ah[4][4], al[4][4], bh[4][2], bl[4][2];
#pragma unroll
            for (int mi = 0; mi < 4; mi++) {
                uint32_t a = sb + SM_AH + (wm * 64 + mi * 16 + lrow) * 144 + kc * 32 + lcol;
                ldsm_x4(ah[mi], a);
                ldsm_x4(al[mi], a + TILE_B);
            }
#pragma unroll
            for (int n2 = 0; n2 < 2; n2++) {
                uint32_t r0[4], r1[4];
                uint32_t b = sb + SM_BH + (wn * 32 + n2 * 16 + lrow) * 144 + kc * 32 + lcol;
                ldsm_x4(r0, b);
                ldsm_x4(r1, b + TILE_B);
                bh[n2 * 2 + 0][0] = r0[0]; bh[n2 * 2 + 0][1] = r0[2];
                bh[n2 * 2 + 1][0] = r0[1]; bh[n2 * 2 + 1][1] = r0[3];
                bl[n2 * 2 + 0][0] = r1[0]; bl[n2 * 2 + 0][1] = r1[2];
                bl[n2 * 2 + 1][0] = r1[1]; bl[n2 * 2 + 1][1] = r1[3];
            }
#pragma unroll
            for (int mi = 0; mi < 4; mi++)
#pragma unroll
                for (int ni = 0; ni < 4; ni++) {
                    mma_bf16(acc[mi][ni], ah[mi], bh[ni]);
                    mma_bf16(acc[mi][ni], ah[mi], bl[ni]);
                    mma_bf16(acc[mi][ni], al[mi], bh[ni]);
                }
        }
        __syncthreads();
    }
}

// ---------------- generic GEMM kernel (mode 0 plain, 1 logits scatter) ----------------
__global__ __launch_bounds__(256, 1)
void mma_gemm(const __nv_bfloat16* __restrict__ Ahi, const __nv_bfloat16* __restrict__ Alo,
              const __nv_bfloat16* __restrict__ Bhi, const __nv_bfloat16* __restrict__ Blo,
              const float* __restrict__ bias, float* __restrict__ Cout,
              int ldc, int nmax, int mode) {
    extern __shared__ char sm[];
    float acc[4][4][4];
#pragma unroll
    for (int a = 0; a < 4; a++)
#pragma unroll
        for (int b = 0; b < 4; b++)
#pragma unroll
            for (int c = 0; c < 4; c++) acc[a][b][c] = 0.0f;

    gemm_mainloop(sm, Ahi, Alo, blockIdx.y * 128, Bhi, Blo, blockIdx.x * 128, acc);

    const int lane = threadIdx.x & 31;
    const int w    = threadIdx.x >> 5;
    const int wm   = w & 1, wn = w >> 1;

#pragma unroll
    for (int mi = 0; mi < 4; mi++)
#pragma unroll
        for (int ni = 0; ni < 4; ni++) {
            int m = blockIdx.y * 128 + wm * 64 + mi * 16 + (lane >> 2);
            int n = blockIdx.x * 128 + wn * 32 + ni * 8 + (lane & 3) * 2;
            float v0 = acc[mi][ni][0];
            float v1 = acc[mi][ni][1];
            float v2 = acc[mi][ni][2];
            float v3 = acc[mi][ni][3];
            if (mode == 0) {
                Cout[(size_t)m * ldc + n]           = v0 + bias[n];
                Cout[(size_t)m * ldc + n + 1]       = v1 + bias[n + 1];
                Cout[(size_t)(m + 8) * ldc + n]     = v2 + bias[n];
                Cout[(size_t)(m + 8) * ldc + n + 1] = v3 + bias[n + 1];
            } else {
                int t0 = m >> 7, b0 = m & 127;
                int t1 = (m + 8) >> 7, b1 = (m + 8) & 127;
                float* d0 = Cout + (size_t)b0 * OUTROW + (size_t)(t0 + 1) * VV;
                float* d1 = Cout + (size_t)b1 * OUTROW + (size_t)(t1 + 1) * VV;
                if (n < nmax)     { d0[n]     = v0 + bias[n];     d1[n]     = v2 + bias[n]; }
                if (n + 1 < nmax) { d0[n + 1] = v1 + bias[n + 1]; d1[n + 1] = v3 + bias[n + 1]; }
            }
        }
}

// ---------------- LSTM step: gates = h @ Whh'^T + Xg -> cell -> new h ----------------
// Permuted gate cols: np = j*4+g. Within an 8-col n-frag, lanes pair up:
// even lane (t even) holds (i,f), odd holds (g,o) of the same j -> one shfl_xor(1).
__global__ __launch_bounds__(256, 1)
void mma_step(int t) {
    extern __shared__ char sm[];
    const int ping = t & 1;
    const __nv_bfloat16* hih = ping ? g_hBhi : g_hAhi;
    const __nv_bfloat16* hil = ping ? g_hBlo : g_hAlo;
    __nv_bfloat16* hoh = ping ? g_hAhi : g_hBhi;
    __nv_bfloat16* hol = ping ? g_hAlo : g_hBlo;

    float acc[4][4][4];
#pragma unroll
    for (int a = 0; a < 4; a++)
#pragma unroll
        for (int b = 0; b < 4; b++)
#pragma unroll
            for (int c = 0; c < 4; c++) acc[a][b][c] = 0.0f;

    gemm_mainloop(sm, hih, hil, 0, g_Whhhi, g_Whhlo, blockIdx.x * 128, acc);

    const int lane = threadIdx.x & 31;
    const int w    = threadIdx.x >> 5;
    const int wm   = w & 1, wn = w >> 1;
    const int tpar = lane & 1;

#pragma unroll
    for (int mi = 0; mi < 4; mi++)
#pragma unroll
        for (int ni = 0; ni < 4; ni++) {
            int m = wm * 64 + mi * 16 + (lane >> 2);       // batch row (0..119)
            int n = blockIdx.x * 128 + wn * 32 + ni * 8 + (lane & 3) * 2;  // permuted gate col
            int r = t * 128 + m;
            const float* xg = g_Xg + (size_t)r * G4;

            float c0 = acc[mi][ni][0] + xg[n];
            float c1 = acc[mi][ni][1] + xg[n + 1];
            float c2 = acc[mi][ni][2] + xg[8 * G4 + n];
            float c3 = acc[mi][ni][3] + xg[8 * G4 + n + 1];

            float e0 = __shfl_xor_sync(0xFFFFFFFFu, c0, 1);
            float e1 = __shfl_xor_sync(0xFFFFFFFFu, c1, 1);
            float e2 = __shfl_xor_sync(0xFFFFFFFFu, c2, 1);
            float e3 = __shfl_xor_sync(0xFFFFFFFFu, c3, 1);

            int   row, j = n >> 2;
            float iv, fv, gv, ov;
            if (!tpar) { row = m;     iv = c0; fv = c1; gv = e0; ov = e1; }
            else       { row = m + 8; iv = e2; fv = e3; gv = c2; ov = c3; }

            float cO = g_c[row * HH + j];
            float cN = sigf(fv) * cO + sigf(iv) * tanhf(gv);
            float hN = sigf(ov) * tanhf(cN);
            g_c[row * HH + j] = cN;

            __nv_bfloat16 hh, hl;
            split2(hN, hh, hl);
            hoh[row * HH + j] = hh;
            hol[row * HH + j] = hl;
            int rr = t * 128 + row;
            g_Hhi[(size_t)rr * HH + j] = hh;
            g_Hlo[(size_t)rr * HH + j] = hl;
        }
}

// ---------------- prep kernels ----------------
__global__ void k_init(const float* __restrict__ img,
                       const float* __restrict__ bih,
                       const float* __restrict__ bhh) {
    int i = blockIdx.x * blockDim.x + threadIdx.x;
    if (i < BB * HH) {
        __nv_bfloat16 h, l;
        split2(img[i], h, l);
        g_hAhi[i] = h; g_hAlo[i] = l;
        g_c[i] = 0.0f;
    }
    if (i < G4) {   // permuted bias: rp = j*4+g  <-  g*512+j
        int j = i >> 2, g = i & 3;
        g_bias[i] = bih[g * HH + j] + bhh[g * HH + j];
    }
}

__global__ void k_embed(const int* __restrict__ caps, const float* __restrict__ Wemb) {
    int idx = blockIdx.x * blockDim.x + threadIdx.x;    // over BTR*128 float4 groups
    if (idx >= BTR * 128) return;
    int e4 = idx & 127, r = idx >> 7;
    int t = r >> 7, b = r & 127;
    int tok = caps[b * TT + t];
    float4 v = make_float4(0.f, 0.f, 0.f, 0.f);
    if (tok != 0) v = *(const float4*)(Wemb + (size_t)tok * EE + e4 * 4);
    int base = r * EE + e4 * 4;
    __nv_bfloat16 h, l;
    split2(v.x, h, l); g_Xhi[base + 0] = h; g_Xlo[base + 0] = l;
    split2(v.y, h, l); g_Xhi[base + 1] = h; g_Xlo[base + 1] = l;
    split2(v.z, h, l); g_Xhi[base + 2] = h; g_Xlo[base + 2] = l;
    split2(v.w, h, l); g_Xhi[base + 3] = h; g_Xlo[base + 3] = l;
}

// permuted split for W_ih / W_hh: dst row rp = j*4+g <- src row g*512+j
__global__ void k_split_perm(const float* __restrict__ W,
                             __nv_bfloat16* __restrict__ hi,
                             __nv_bfloat16* __restrict__ lo) {
    int idx = blockIdx.x * blockDim.x + threadIdx.x;    // over G4*128 float4 groups
    if (idx >= G4 * 128) return;
    int k4 = idx & 127, rp = idx >> 7;
    int j = rp >> 2, g = rp & 3;
    float4 v = *(const float4*)(W + (size_t)(g * HH + j) * 512 + k4 * 4);
    int base = rp * 512 + k4 * 4;
    __nv_bfloat16 h, l;
    split2(v.x, h, l); hi[base + 0] = h; lo[base + 0] = l;
    split2(v.y, h, l); hi[base + 1] = h; lo[base + 1] = l;
    split2(v.z, h, l); hi[base + 2] = h; lo[base + 2] = l;
    split2(v.w, h, l); hi[base + 3] = h; lo[base + 3] = l;
}

__global__ void k_split_out(const float* __restrict__ W) {
    int idx = blockIdx.x * blockDim.x + threadIdx.x;    // over NPAD*128 float4 groups
    if (idx >= NPAD * 128) return;
    int k4 = idx & 127, r = idx >> 7;
    float4 v = make_float4(0.f, 0.f, 0.f, 0.f);
    if (r < VV) v = *(const float4*)(W + (size_t)r * HH + k4 * 4);
    int base = r * 512 + k4 * 4;
    __nv_bfloat16 h, l;
    split2(v.x, h, l); g_Wouthi[base + 0] = h; g_Woutlo[base + 0] = l;
    split2(v.y, h, l); g_Wouthi[base + 1] = h; g_Woutlo[base + 1] = l;
    split2(v.z, h, l); g_Wouthi[base + 2] = h; g_Woutlo[base + 2] = l;
    split2(v.w, h, l); g_Wouthi[base + 3] = h; g_Woutlo[base + 3] = l;
}

__global__ void k_start(float* __restrict__ out, const int* __restrict__ clen, int extra) {
    int i = blockIdx.x * blockDim.x + threadIdx.x;
    const int n = BB * VV;
    if (i < n) {
        int b = i / VV;
        int v = i - b * VV;
        out[(size_t)b * OUTROW + v] = (v == 1) ? 1.0f : 0.0f;
    }
    if (i < extra) {
        float val = (i < BB) ? (float)(clen[i] - 1) : 0.0f;
        out[(size_t)BB * OUTROW + i] = val;
    }
}

// ---------------- launch ----------------
extern "C" void kernel_launch(void* const* d_in, const int* in_sizes, int n_in,
                              void* d_out, int out_size) {
    const float* images = (const float*)d_in[0];
    const int*   caps   = (const int*)  d_in[1];
    const int*   clen   = (const int*)  d_in[2];
    const float* Wemb   = (const float*)d_in[3];
    const float* Wih    = (const float*)d_in[4];
    const float* Whh    = (const float*)d_in[5];
    const float* bih    = (const float*)d_in[6];
    const float* bhh    = (const float*)d_in[7];
    const float* Wout   = (const float*)d_in[8];
    const float* bout   = (const float*)d_in[9];
    float* out = (float*)d_out;

    cudaFuncSetAttribute(mma_gemm, cudaFuncAttributeMaxDynamicSharedMemorySize, SMEM_DYN);
    cudaFuncSetAttribute(mma_step, cudaFuncAttributeMaxDynamicSharedMemorySize, SMEM_DYN);

    const __nv_bfloat16 *pXhi, *pXlo, *pWihhi, *pWihlo, *pWouthi, *pWoutlo, *pHhi, *pHlo;
    float *pbias, *pXg;
    cudaGetSymbolAddress((void**)&pXhi,    g_Xhi);
    cudaGetSymbolAddress((void**)&pXlo,    g_Xlo);
    cudaGetSymbolAddress((void**)&pWihhi,  g_Wihhi);
    cudaGetSymbolAddress((void**)&pWihlo,  g_Wihlo);
    cudaGetSymbolAddress((void**)&pWouthi, g_Wouthi);
    cudaGetSymbolAddress((void**)&pWoutlo, g_Woutlo);
    cudaGetSymbolAddress((void**)&pHhi,    g_Hhi);
    cudaGetSymbolAddress((void**)&pHlo,    g_Hlo);
    cudaGetSymbolAddress((void**)&pbias,   g_bias);
    cudaGetSymbolAddress((void**)&pXg,     g_Xg);

    __nv_bfloat16 *pWhhhi, *pWhhlo;
    cudaGetSymbolAddress((void**)&pWhhhi, g_Whhhi);
    cudaGetSymbolAddress((void**)&pWhhlo, g_Whhlo);

    // 1. init: h0 planes, c0, permuted bias
    k_init<<<(BB * HH + 255) / 256, 256>>>(images, bih, bhh);

    // 2. embedding -> bf16 hi/lo planes
    k_embed<<<(BTR * 128 + 255) / 256, 256>>>(caps, Wemb);

    // 3. weight splits
    k_split_perm<<<(G4 * 128 + 255) / 256, 256>>>(Wih, (__nv_bfloat16*)pWihhi, (__nv_bfloat16*)pWihlo);
    k_split_perm<<<(G4 * 128 + 255) / 256, 256>>>(Whh, pWhhhi, pWhhlo);
    k_split_out <<<(NPAD * 128 + 255) / 256, 256>>>(Wout);

    // 4. Xg = X @ Wih'^T + bias'   [3072 x 2048]
    {
        dim3 grid(G4 / 128, BTR / 128);
        mma_gemm<<<grid, 256, SMEM_DYN>>>(pXhi, pXlo, pWihhi, pWihlo,
                                          pbias, pXg, G4, G4, 0);
    }

    // 5. recurrence: 24 HMMA steps with fused cell epilogue
    for (int t = 0; t < TT; t++)
        mma_step<<<dim3(G4 / 128, 1), 256, SMEM_DYN>>>(t);

    // 6. logits = H_all @ Wout^T + b_out -> scatter into d_out
    {
        dim3 grid(NPAD / 128, BTR / 128);
        mma_gemm<<<grid, 256, SMEM_DYN>>>(pHhi, pHlo, pWouthi, pWoutlo,
                                          bout, out, VV, VV, 1);
    }

    // 7. t=0 one-hot rows + optional length tail
    {
        int extra = out_size - BB * OUTROW;
        if (extra < 0) extra = 0;
        k_start<<<(BB * VV + 255) / 256, 256>>>(out, clen, extra);
    }
}

// round 10
// speedup vs baseline: 1.0536x; 1.0536x over previous
#include <cuda_runtime.h>
#include <cuda_bf16.h>
#include <math.h>
#include <stdint.h>

#define BB   128
#define TT   24
#define EE   512
#define HH   512
#define VV   10000
#define G4   2048
#define BTR  3072
#define OUTROW 250000
#define NPAD 10112          // 79 * 128  (padded vocab rows)

// ---------------- device scratch (no allocations allowed) ----------------
__device__ __nv_bfloat16 g_Xhi [BTR * EE], g_Xlo [BTR * EE];     // embedded captions
__device__ __nv_bfloat16 g_Wihhi[G4 * EE], g_Wihlo[G4 * EE];     // permuted W_ih
__device__ __nv_bfloat16 g_Whhhi[G4 * HH], g_Whhlo[G4 * HH];     // permuted W_hh
__device__ __nv_bfloat16 g_Wouthi[NPAD * HH], g_Woutlo[NPAD * HH];
__device__ __nv_bfloat16 g_Hhi [BTR * HH], g_Hlo [BTR * HH];     // all hidden states
__device__ __nv_bfloat16 g_hAhi[BB * HH], g_hAlo[BB * HH];
__device__ __nv_bfloat16 g_hBhi[BB * HH], g_hBlo[BB * HH];
__device__ float g_c   [BB * HH];
__device__ float g_bias[G4];                                     // permuted b_ih+b_hh
__device__ float g_Xg  [BTR * G4];                               // input gates (permuted cols)

// ---------------- small helpers ----------------
__device__ __forceinline__ float sigf(float x) { return 1.0f / (1.0f + expf(-x)); }

__device__ __forceinline__ void split2(float x, __nv_bfloat16& h, __nv_bfloat16& l) {
    h = __float2bfloat16(x);
    l = __float2bfloat16(x - __bfloat162float(h));
}

__device__ __forceinline__ uint32_t smem_to_u32(const void* p) {
    uint32_t a;
    asm("{ .reg .u64 t; cvta.to.shared.u64 t, %1; cvt.u32.u64 %0, t; }" : "=r"(a) : "l"(p));
    return a;
}

// ---------------- warp-level tensor ops (sm_80+ PTX; legal on plain sm_103) ----
__device__ __forceinline__ void ldsm_x4(uint32_t* r, uint32_t addr) {
    asm volatile("ldmatrix.sync.aligned.m8n8.x4.shared.b16 {%0,%1,%2,%3}, [%4];"
                 : "=r"(r[0]), "=r"(r[1]), "=r"(r[2]), "=r"(r[3]) : "r"(addr));
}

__device__ __forceinline__ void mma_bf16(float* c, const uint32_t* a, const uint32_t* b) {
    asm volatile(
        "mma.sync.aligned.m16n8k16.row.col.f32.bf16.bf16.f32 "
        "{%0,%1,%2,%3}, {%4,%5,%6,%7}, {%8,%9}, {%0,%1,%2,%3};"
        : "+f"(c[0]), "+f"(c[1]), "+f"(c[2]), "+f"(c[3])
        : "r"(a[0]), "r"(a[1]), "r"(a[2]), "r"(a[3]), "r"(b[0]), "r"(b[1]));
}

// ---------------- cp.async (sm_80+ PTX) ----------------
__device__ __forceinline__ void cp_async16(uint32_t dst, const void* src) {
    asm volatile("cp.async.cg.shared.global [%0], [%1], 16;" :: "r"(dst), "l"(src));
}
#define CP_COMMIT()   asm volatile("cp.async.commit_group;" ::: "memory")
#define CP_WAIT_ALL() asm volatile("cp.async.wait_group 0;" ::: "memory")

// ---------------- smem layout ----------------
// Plane = 128 rows x 64 bf16 k, rows padded to 144B -> 18432 B.
// Row stride 144B = 36 words; 36 mod 32 = 4 => 8 consecutive rows cover all 32
// banks with their 4-word ldmatrix segments: conflict-free.
// 4 planes (Ahi,Alo,Bhi,Blo) per stage; 2 stages double-buffered.
#define TILE_B   (128 * 144)
#define SM_AH    0
#define SM_AL    (1 * TILE_B)
#define SM_BH    (2 * TILE_B)
#define SM_BL    (3 * TILE_B)
#define STAGE_B  (4 * TILE_B)       // 73728
#define SMEM_DYN (2 * STAGE_B)      // 147456

// Async-load one 128x64 bf16 tile (gmem ld = 512) into padded smem rows.
__device__ __forceinline__ void load_tile_async(uint32_t dst, const __nv_bfloat16* src,
                                                int row0, int k0, int tid) {
#pragma unroll
    for (int i = 0; i < 4; i++) {
        int e  = tid + i * 256;           // 0..1023 groups of 8 bf16
        int r  = e >> 3;                  // 0..127
        int k8 = (e & 7) << 3;            // 0..56
        cp_async16(dst + r * 144 + k8 * 2,
                   src + (size_t)(row0 + r) * 512 + k0 + k8);
    }
}

__device__ __forceinline__ void load_stage(uint32_t stage,
        const __nv_bfloat16* Ahi, const __nv_bfloat16* Alo, int arow0,
        const __nv_bfloat16* Bhi, const __nv_bfloat16* Blo, int brow0,
        int k0, int tid) {
    load_tile_async(stage + SM_AH, Ahi, arow0, k0, tid);
    load_tile_async(stage + SM_AL, Alo, arow0, k0, tid);
    load_tile_async(stage + SM_BH, Bhi, brow0, k0, tid);
    load_tile_async(stage + SM_BL, Blo, brow0, k0, tid);
    CP_COMMIT();
}

// ---------------- shared mainloop (2-stage cp.async pipeline) ----------------
// acc[mi][ni][4] += A(hi+lo)[128xK] @ B(hi+lo)[128xK]^T  (3-product bf16 emulation)
// Warp grid: 8 warps = 2(m) x 4(n); warp tile 64m x 32n; K = 512, K-tile 64.
__device__ __forceinline__ void gemm_mainloop(char* sm,
        const __nv_bfloat16* Ahi, const __nv_bfloat16* Alo, int arow0,
        const __nv_bfloat16* Bhi, const __nv_bfloat16* Blo, int brow0,
        float acc[4][4][4]) {
    const int tid  = threadIdx.x;
    const int lane = tid & 31;
    const int w    = tid >> 5;
    const int wm   = w & 1;
    const int wn   = w >> 1;
    const uint32_t sb = smem_to_u32(sm);

    const int lrow = lane & 15;
    const int lcol = (lane >> 4) * 16;    // byte offset within 32B k16 chunk

    // preload K-tile 0 into stage 0
    load_stage(sb, Ahi, Alo, arow0, Bhi, Blo, brow0, 0, tid);

    for (int kt = 0; kt < 8; kt++) {
        const uint32_t cur = sb + (kt & 1) * STAGE_B;
        CP_WAIT_ALL();
        __syncthreads();
        if (kt + 1 < 8)
            load_stage(sb + ((kt + 1) & 1) * STAGE_B,
                       Ahi, Alo, arow0, Bhi, Blo, brow0, (kt + 1) * 64, tid);

#pragma unroll
        for (int kc = 0; kc < 4; kc++) {
            uint32_t ah[4][4], al[4][4], bh[4][2], bl[4][2];
#pragma unroll
            for (int mi = 0; mi < 4; mi++) {
                uint32_t a = cur + SM_AH + (wm * 64 + mi * 16 + lrow) * 144 + kc * 32 + lcol;
                ldsm_x4(ah[mi], a);
                ldsm_x4(al[mi], a + TILE_B);
            }
#pragma unroll
            for (int n2 = 0; n2 < 2; n2++) {
                uint32_t r0[4], r1[4];
                uint32_t b = cur + SM_BH + (wn * 32 + n2 * 16 + lrow) * 144 + kc * 32 + lcol;
                ldsm_x4(r0, b);
                ldsm_x4(r1, b + TILE_B);
                bh[n2 * 2 + 0][0] = r0[0]; bh[n2 * 2 + 0][1] = r0[2];
                bh[n2 * 2 + 1][0] = r0[1]; bh[n2 * 2 + 1][1] = r0[3];
                bl[n2 * 2 + 0][0] = r1[0]; bl[n2 * 2 + 0][1] = r1[2];
                bl[n2 * 2 + 1][0] = r1[1]; bl[n2 * 2 + 1][1] = r1[3];
            }
#pragma unroll
            for (int mi = 0; mi < 4; mi++)
#pragma unroll
                for (int ni = 0; ni < 4; ni++) {
                    mma_bf16(acc[mi][ni], ah[mi], bh[ni]);
                    mma_bf16(acc[mi][ni], ah[mi], bl[ni]);
                    mma_bf16(acc[mi][ni], al[mi], bh[ni]);
                }
        }
        __syncthreads();   // all warps done reading `cur` before kt+1 overwrites it
    }
}

// ---------------- generic GEMM kernel (mode 0 plain, 1 logits scatter) ----------------
__global__ __launch_bounds__(256, 1)
void mma_gemm(const __nv_bfloat16* __restrict__ Ahi, const __nv_bfloat16* __restrict__ Alo,
              const __nv_bfloat16* __restrict__ Bhi, const __nv_bfloat16* __restrict__ Blo,
              const float* __restrict__ bias, float* __restrict__ Cout,
              int ldc, int nmax, int mode) {
    extern __shared__ char sm[];
    float acc[4][4][4];
#pragma unroll
    for (int a = 0; a < 4; a++)
#pragma unroll
        for (int b = 0; b < 4; b++)
#pragma unroll
            for (int c = 0; c < 4; c++) acc[a][b][c] = 0.0f;

    gemm_mainloop(sm, Ahi, Alo, blockIdx.y * 128, Bhi, Blo, blockIdx.x * 128, acc);

    const int lane = threadIdx.x & 31;
    const int w    = threadIdx.x >> 5;
    const int wm   = w & 1, wn = w >> 1;

#pragma unroll
    for (int mi = 0; mi < 4; mi++)
#pragma unroll
        for (int ni = 0; ni < 4; ni++) {
            int m = blockIdx.y * 128 + wm * 64 + mi * 16 + (lane >> 2);
            int n = blockIdx.x * 128 + wn * 32 + ni * 8 + (lane & 3) * 2;
            float v0 = acc[mi][ni][0];
            float v1 = acc[mi][ni][1];
            float v2 = acc[mi][ni][2];
            float v3 = acc[mi][ni][3];
            if (mode == 0) {
                Cout[(size_t)m * ldc + n]           = v0 + bias[n];
                Cout[(size_t)m * ldc + n + 1]       = v1 + bias[n + 1];
                Cout[(size_t)(m + 8) * ldc + n]     = v2 + bias[n];
                Cout[(size_t)(m + 8) * ldc + n + 1] = v3 + bias[n + 1];
            } else {
                int t0 = m >> 7, b0 = m & 127;
                int t1 = (m + 8) >> 7, b1 = (m + 8) & 127;
                float* d0 = Cout + (size_t)b0 * OUTROW + (size_t)(t0 + 1) * VV;
                float* d1 = Cout + (size_t)b1 * OUTROW + (size_t)(t1 + 1) * VV;
                if (n < nmax)     { d0[n]     = v0 + bias[n];     d1[n]     = v2 + bias[n]; }
                if (n + 1 < nmax) { d0[n + 1] = v1 + bias[n + 1]; d1[n + 1] = v3 + bias[n + 1]; }
            }
        }
}

// ---------------- LSTM step: gates = h @ Whh'^T + Xg -> cell -> new h ----------------
// Permuted gate cols: np = j*4+g. Within an 8-col n-frag, lanes pair up:
// even lane holds (i,f), odd holds (g,o) of the same j -> one shfl_xor(1).
__global__ __launch_bounds__(256, 1)
void mma_step(int t) {
    extern __shared__ char sm[];
    const int ping = t & 1;
    const __nv_bfloat16* hih = ping ? g_hBhi : g_hAhi;
    const __nv_bfloat16* hil = ping ? g_hBlo : g_hAlo;
    __nv_bfloat16* hoh = ping ? g_hAhi : g_hBhi;
    __nv_bfloat16* hol = ping ? g_hAlo : g_hBlo;

    float acc[4][4][4];
#pragma unroll
    for (int a = 0; a < 4; a++)
#pragma unroll
        for (int b = 0; b < 4; b++)
#pragma unroll
            for (int c = 0; c < 4; c++) acc[a][b][c] = 0.0f;

    gemm_mainloop(sm, hih, hil, 0, g_Whhhi, g_Whhlo, blockIdx.x * 128, acc);

    const int lane = threadIdx.x & 31;
    const int w    = threadIdx.x >> 5;
    const int wm   = w & 1, wn = w >> 1;
    const int tpar = lane & 1;

#pragma unroll
    for (int mi = 0; mi < 4; mi++)
#pragma unroll
        for (int ni = 0; ni < 4; ni++) {
            int m = wm * 64 + mi * 16 + (lane >> 2);       // batch row (0..119)
            int n = blockIdx.x * 128 + wn * 32 + ni * 8 + (lane & 3) * 2;  // permuted gate col
            int r = t * 128 + m;
            const float* xg = g_Xg + (size_t)r * G4;

            float c0 = acc[mi][ni][0] + xg[n];
            float c1 = acc[mi][ni][1] + xg[n + 1];
            float c2 = acc[mi][ni][2] + xg[8 * G4 + n];
            float c3 = acc[mi][ni][3] + xg[8 * G4 + n + 1];

            float e0 = __shfl_xor_sync(0xFFFFFFFFu, c0, 1);
            float e1 = __shfl_xor_sync(0xFFFFFFFFu, c1, 1);
            float e2 = __shfl_xor_sync(0xFFFFFFFFu, c2, 1);
            float e3 = __shfl_xor_sync(0xFFFFFFFFu, c3, 1);

            int   row, j = n >> 2;
            float iv, fv, gv, ov;
            if (!tpar) { row = m;     iv = c0; fv = c1; gv = e0; ov = e1; }
            else       { row = m + 8; iv = e2; fv = e3; gv = c2; ov = c3; }

            float cO = g_c[row * HH + j];
            float cN = sigf(fv) * cO + sigf(iv) * tanhf(gv);
            float hN = sigf(ov) * tanhf(cN);
            g_c[row * HH + j] = cN;

            __nv_bfloat16 hh, hl;
            split2(hN, hh, hl);
            hoh[row * HH + j] = hh;
            hol[row * HH + j] = hl;
            int rr = t * 128 + row;
            g_Hhi[(size_t)rr * HH + j] = hh;
            g_Hlo[(size_t)rr * HH + j] = hl;
        }
}

// ---------------- prep kernels ----------------
__global__ void k_init(const float* __restrict__ img,
                       const float* __restrict__ bih,
                       const float* __restrict__ bhh) {
    int i = blockIdx.x * blockDim.x + threadIdx.x;
    if (i < BB * HH) {
        __nv_bfloat16 h, l;
        split2(img[i], h, l);
        g_hAhi[i] = h; g_hAlo[i] = l;
        g_c[i] = 0.0f;
    }
    if (i < G4) {   // permuted bias: rp = j*4+g  <-  g*512+j
        int j = i >> 2, g = i & 3;
        g_bias[i] = bih[g * HH + j] + bhh[g * HH + j];
    }
}

__global__ void k_embed(const int* __restrict__ caps, const float* __restrict__ Wemb) {
    int idx = blockIdx.x * blockDim.x + threadIdx.x;    // over BTR*128 float4 groups
    if (idx >= BTR * 128) return;
    int e4 = idx & 127, r = idx >> 7;
    int t = r >> 7, b = r & 127;
    int tok = caps[b * TT + t];
    float4 v = make_float4(0.f, 0.f, 0.f, 0.f);
    if (tok != 0) v = *(const float4*)(Wemb + (size_t)tok * EE + e4 * 4);
    int base = r * EE + e4 * 4;
    __nv_bfloat16 h, l;
    split2(v.x, h, l); g_Xhi[base + 0] = h; g_Xlo[base + 0] = l;
    split2(v.y, h, l); g_Xhi[base + 1] = h; g_Xlo[base + 1] = l;
    split2(v.z, h, l); g_Xhi[base + 2] = h; g_Xlo[base + 2] = l;
    split2(v.w, h, l); g_Xhi[base + 3] = h; g_Xlo[base + 3] = l;
}

// permuted split for W_ih / W_hh: dst row rp = j*4+g <- src row g*512+j
__global__ void k_split_perm(const float* __restrict__ W,
                             __nv_bfloat16* __restrict__ hi,
                             __nv_bfloat16* __restrict__ lo) {
    int idx = blockIdx.x * blockDim.x + threadIdx.x;    // over G4*128 float4 groups
    if (idx >= G4 * 128) return;
    int k4 = idx & 127, rp = idx >> 7;
    int j = rp >> 2, g = rp & 3;
    float4 v = *(const float4*)(W + (size_t)(g * HH + j) * 512 + k4 * 4);
    int base = rp * 512 + k4 * 4;
    __nv_bfloat16 h, l;
    split2(v.x, h, l); hi[base + 0] = h; lo[base + 0] = l;
    split2(v.y, h, l); hi[base + 1] = h; lo[base + 1] = l;
    split2(v.z, h, l); hi[base + 2] = h; lo[base + 2] = l;
    split2(v.w, h, l); hi[base + 3] = h; lo[base + 3] = l;
}

__global__ void k_split_out(const float* __restrict__ W) {
    int idx = blockIdx.x * blockDim.x + threadIdx.x;    // over NPAD*128 float4 groups
    if (idx >= NPAD * 128) return;
    int k4 = idx & 127, r = idx >> 7;
    float4 v = make_float4(0.f, 0.f, 0.f, 0.f);
    if (r < VV) v = *(const float4*)(W + (size_t)r * HH + k4 * 4);
    int base = r * 512 + k4 * 4;
    __nv_bfloat16 h, l;
    split2(v.x, h, l); g_Wouthi[base + 0] = h; g_Woutlo[base + 0] = l;
    split2(v.y, h, l); g_Wouthi[base + 1] = h; g_Woutlo[base + 1] = l;
    split2(v.z, h, l); g_Wouthi[base + 2] = h; g_Woutlo[base + 2] = l;
    split2(v.w, h, l); g_Wouthi[base + 3] = h; g_Woutlo[base + 3] = l;
}

__global__ void k_start(float* __restrict__ out, const int* __restrict__ clen, int extra) {
    int i = blockIdx.x * blockDim.x + threadIdx.x;
    const int n = BB * VV;
    if (i < n) {
        int b = i / VV;
        int v = i - b * VV;
        out[(size_t)b * OUTROW + v] = (v == 1) ? 1.0f : 0.0f;
    }
    if (i < extra) {
        float val = (i < BB) ? (float)(clen[i] - 1) : 0.0f;
        out[(size_t)BB * OUTROW + i] = val;
    }
}

// ---------------- launch ----------------
extern "C" void kernel_launch(void* const* d_in, const int* in_sizes, int n_in,
                              void* d_out, int out_size) {
    const float* images = (const float*)d_in[0];
    const int*   caps   = (const int*)  d_in[1];
    const int*   clen   = (const int*)  d_in[2];
    const float* Wemb   = (const float*)d_in[3];
    const float* Wih    = (const float*)d_in[4];
    const float* Whh    = (const float*)d_in[5];
    const float* bih    = (const float*)d_in[6];
    const float* bhh    = (const float*)d_in[7];
    const float* Wout   = (const float*)d_in[8];
    const float* bout   = (const float*)d_in[9];
    float* out = (float*)d_out;

    cudaFuncSetAttribute(mma_gemm, cudaFuncAttributeMaxDynamicSharedMemorySize, SMEM_DYN);
    cudaFuncSetAttribute(mma_step, cudaFuncAttributeMaxDynamicSharedMemorySize, SMEM_DYN);

    const __nv_bfloat16 *pXhi, *pXlo, *pWihhi, *pWihlo, *pWouthi, *pWoutlo, *pHhi, *pHlo;
    float *pbias, *pXg;
    cudaGetSymbolAddress((void**)&pXhi,    g_Xhi);
    cudaGetSymbolAddress((void**)&pXlo,    g_Xlo);
    cudaGetSymbolAddress((void**)&pWihhi,  g_Wihhi);
    cudaGetSymbolAddress((void**)&pWihlo,  g_Wihlo);
    cudaGetSymbolAddress((void**)&pWouthi, g_Wouthi);
    cudaGetSymbolAddress((void**)&pWoutlo, g_Woutlo);
    cudaGetSymbolAddress((void**)&pHhi,    g_Hhi);
    cudaGetSymbolAddress((void**)&pHlo,    g_Hlo);
    cudaGetSymbolAddress((void**)&pbias,   g_bias);
    cudaGetSymbolAddress((void**)&pXg,     g_Xg);

    __nv_bfloat16 *pWhhhi, *pWhhlo;
    cudaGetSymbolAddress((void**)&pWhhhi, g_Whhhi);
    cudaGetSymbolAddress((void**)&pWhhlo, g_Whhlo);

    // 1. init: h0 planes, c0, permuted bias
    k_init<<<(BB * HH + 255) / 256, 256>>>(images, bih, bhh);

    // 2. embedding -> bf16 hi/lo planes
    k_embed<<<(BTR * 128 + 255) / 256, 256>>>(caps, Wemb);

    // 3. weight splits
    k_split_perm<<<(G4 * 128 + 255) / 256, 256>>>(Wih, (__nv_bfloat16*)pWihhi, (__nv_bfloat16*)pWihlo);
    k_split_perm<<<(G4 * 128 + 255) / 256, 256>>>(Whh, pWhhhi, pWhhlo);
    k_split_out <<<(NPAD * 128 + 255) / 256, 256>>>(Wout);

    // 4. Xg = X @ Wih'^T + bias'   [3072 x 2048]
    {
        dim3 grid(G4 / 128, BTR / 128);
        mma_gemm<<<grid, 256, SMEM_DYN>>>(pXhi, pXlo, pWihhi, pWihlo,
                                          pbias, pXg, G4, G4, 0);
    }

    // 5. recurrence: 24 HMMA steps with fused cell epilogue
    for (int t = 0; t < TT; t++)
        mma_step<<<dim3(G4 / 128, 1), 256, SMEM_DYN>>>(t);

    // 6. logits = H_all @ Wout^T + b_out -> scatter into d_out
    {
        dim3 grid(NPAD / 128, BTR / 128);
        mma_gemm<<<grid, 256, SMEM_DYN>>>(pHhi, pHlo, pWouthi, pWoutlo,
                                          bout, out, VV, VV, 1);
    }

    // 7. t=0 one-hot rows + optional length tail
    {
        int extra = out_size - BB * OUTROW;
        if (extra < 0) extra = 0;
        k_start<<<(BB * VV + 255) / 256, 256>>>(out, clen, extra);
    }
}

// round 11
// speedup vs baseline: 1.8285x; 1.7355x over previous
#include <cuda_runtime.h>
#include <cuda_fp16.h>
#include <math.h>
#include <stdint.h>

#define BB   128
#define TT   24
#define EE   512
#define HH   512
#define VV   10000
#define G4   2048
#define BTR  3072
#define OUTROW 250000
#define NPAD 10112          // 79 * 128  (padded vocab rows)

// ---------------- device scratch (no allocations allowed) ----------------
__device__ __half g_X   [BTR * EE];        // embedded captions (fp16)
__device__ __half g_Wih [G4 * EE];         // permuted W_ih (fp16)
__device__ __half g_Whh [G4 * HH];         // permuted W_hh (fp16)
__device__ __half g_Wout[NPAD * HH];       // padded W_out (fp16)
__device__ __half g_Hall[BTR * HH];        // all hidden states (fp16)
__device__ __half g_hA  [BB * HH];
__device__ __half g_hB  [BB * HH];
__device__ float  g_c   [BB * HH];
__device__ float  g_bias[G4];              // permuted b_ih+b_hh
__device__ float  g_Xg  [BTR * G4];        // input gates (permuted cols)
__device__ int    g_ctr;                   // recurrence spin-barrier counter

// ---------------- small helpers ----------------
__device__ __forceinline__ float sigf(float x) { return 1.0f / (1.0f + expf(-x)); }

__device__ __forceinline__ uint32_t smem_to_u32(const void* p) {
    uint32_t a;
    asm("{ .reg .u64 t; cvta.to.shared.u64 t, %1; cvt.u32.u64 %0, t; }" : "=r"(a) : "l"(p));
    return a;
}

// ---------------- warp-level tensor ops (sm_80+ PTX; legal on plain sm_103) ----
__device__ __forceinline__ void ldsm_x4(uint32_t* r, uint32_t addr) {
    asm volatile("ldmatrix.sync.aligned.m8n8.x4.shared.b16 {%0,%1,%2,%3}, [%4];"
                 : "=r"(r[0]), "=r"(r[1]), "=r"(r[2]), "=r"(r[3]) : "r"(addr));
}

__device__ __forceinline__ void mma_f16(float* c, const uint32_t* a, const uint32_t* b) {
    asm volatile(
        "mma.sync.aligned.m16n8k16.row.col.f32.f16.f16.f32 "
        "{%0,%1,%2,%3}, {%4,%5,%6,%7}, {%8,%9}, {%0,%1,%2,%3};"
        : "+f"(c[0]), "+f"(c[1]), "+f"(c[2]), "+f"(c[3])
        : "r"(a[0]), "r"(a[1]), "r"(a[2]), "r"(a[3]), "r"(b[0]), "r"(b[1]));
}

// ---------------- cp.async (sm_80+ PTX) ----------------
__device__ __forceinline__ void cp_async16(uint32_t dst, const void* src) {
    asm volatile("cp.async.cg.shared.global [%0], [%1], 16;" :: "r"(dst), "l"(src));
}
#define CP_COMMIT()   asm volatile("cp.async.commit_group;" ::: "memory")
#define CP_WAIT_ALL() asm volatile("cp.async.wait_group 0;" ::: "memory")

// ---------------- smem layout ----------------
// Plane = 128 rows x 64 fp16 k, rows padded to 144B -> 18432 B.
// Row stride 144B = 36 words; 36 mod 32 = 4 => 8 consecutive rows cover all 32
// banks with their 4-word ldmatrix segments: conflict-free.
// 2 planes (A, B) per stage; 2 stages double-buffered.
#define TILE_B   (128 * 144)
#define SM_A     0
#define SM_B     (1 * TILE_B)
#define STAGE_B  (2 * TILE_B)       // 36864
#define SMEM_DYN (2 * STAGE_B)      // 73728

// Async-load one 128x64 fp16 tile (gmem ld = 512) into padded smem rows.
__device__ __forceinline__ void load_tile_async(uint32_t dst, const __half* src,
                                                int row0, int k0, int tid) {
#pragma unroll
    for (int i = 0; i < 4; i++) {
        int e  = tid + i * 256;           // 0..1023 groups of 8 fp16
        int r  = e >> 3;                  // 0..127
        int k8 = (e & 7) << 3;            // 0..56
        cp_async16(dst + r * 144 + k8 * 2,
                   src + (size_t)(row0 + r) * 512 + k0 + k8);
    }
}

__device__ __forceinline__ void load_stage(uint32_t stage,
        const __half* A, int arow0, const __half* Bm, int brow0,
        int k0, int tid) {
    load_tile_async(stage + SM_A, A, arow0, k0, tid);
    load_tile_async(stage + SM_B, Bm, brow0, k0, tid);
    CP_COMMIT();
}

// ---------------- shared mainloop (2-stage cp.async pipeline) ----------------
// acc[mi][ni][4] += A[128xK] @ B[128xK]^T   (fp16 inputs, fp32 accumulate)
// Warp grid: 8 warps = 2(m) x 4(n); warp tile 64m x 32n; K = 512, K-tile 64.
__device__ __forceinline__ void gemm_mainloop(char* sm,
        const __half* A, int arow0, const __half* Bm, int brow0,
        float acc[4][4][4]) {
    const int tid  = threadIdx.x;
    const int lane = tid & 31;
    const int w    = tid >> 5;
    const int wm   = w & 1;
    const int wn   = w >> 1;
    const uint32_t sb = smem_to_u32(sm);

    const int lrow = lane & 15;
    const int lcol = (lane >> 4) * 16;    // byte offset within 32B k16 chunk

    load_stage(sb, A, arow0, Bm, brow0, 0, tid);

    for (int kt = 0; kt < 8; kt++) {
        const uint32_t cur = sb + (kt & 1) * STAGE_B;
        CP_WAIT_ALL();
        __syncthreads();
        if (kt + 1 < 8)
            load_stage(sb + ((kt + 1) & 1) * STAGE_B,
                       A, arow0, Bm, brow0, (kt + 1) * 64, tid);

#pragma unroll
        for (int kc = 0; kc < 4; kc++) {
            uint32_t ah[4][4], bh[4][2];
#pragma unroll
            for (int mi = 0; mi < 4; mi++) {
                uint32_t a = cur + SM_A + (wm * 64 + mi * 16 + lrow) * 144 + kc * 32 + lcol;
                ldsm_x4(ah[mi], a);
            }
#pragma unroll
            for (int n2 = 0; n2 < 2; n2++) {
                uint32_t r0[4];
                uint32_t b = cur + SM_B + (wn * 32 + n2 * 16 + lrow) * 144 + kc * 32 + lcol;
                ldsm_x4(r0, b);
                bh[n2 * 2 + 0][0] = r0[0]; bh[n2 * 2 + 0][1] = r0[2];
                bh[n2 * 2 + 1][0] = r0[1]; bh[n2 * 2 + 1][1] = r0[3];
            }
#pragma unroll
            for (int mi = 0; mi < 4; mi++)
#pragma unroll
                for (int ni = 0; ni < 4; ni++)
                    mma_f16(acc[mi][ni], ah[mi], bh[ni]);
        }
        __syncthreads();   // all warps done reading `cur` before kt+1 overwrites it
    }
}

// ---------------- generic GEMM kernel (mode 0 plain, 1 logits scatter) ----------------
__global__ __launch_bounds__(256, 2)
void mma_gemm(const __half* __restrict__ A, const __half* __restrict__ Bm,
              const float* __restrict__ bias, float* __restrict__ Cout,
              int ldc, int nmax, int mode) {
    extern __shared__ char sm[];
    float acc[4][4][4];
#pragma unroll
    for (int a = 0; a < 4; a++)
#pragma unroll
        for (int b = 0; b < 4; b++)
#pragma unroll
            for (int c = 0; c < 4; c++) acc[a][b][c] = 0.0f;

    gemm_mainloop(sm, A, blockIdx.y * 128, Bm, blockIdx.x * 128, acc);

    const int lane = threadIdx.x & 31;
    const int w    = threadIdx.x >> 5;
    const int wm   = w & 1, wn = w >> 1;

#pragma unroll
    for (int mi = 0; mi < 4; mi++)
#pragma unroll
        for (int ni = 0; ni < 4; ni++) {
            int m = blockIdx.y * 128 + wm * 64 + mi * 16 + (lane >> 2);
            int n = blockIdx.x * 128 + wn * 32 + ni * 8 + (lane & 3) * 2;
            float v0 = acc[mi][ni][0];
            float v1 = acc[mi][ni][1];
            float v2 = acc[mi][ni][2];
            float v3 = acc[mi][ni][3];
            if (mode == 0) {
                Cout[(size_t)m * ldc + n]           = v0 + bias[n];
                Cout[(size_t)m * ldc + n + 1]       = v1 + bias[n + 1];
                Cout[(size_t)(m + 8) * ldc + n]     = v2 + bias[n];
                Cout[(size_t)(m + 8) * ldc + n + 1] = v3 + bias[n + 1];
            } else {
                int t0 = m >> 7, b0 = m & 127;
                int t1 = (m + 8) >> 7, b1 = (m + 8) & 127;
                float* d0 = Cout + (size_t)b0 * OUTROW + (size_t)(t0 + 1) * VV;
                float* d1 = Cout + (size_t)b1 * OUTROW + (size_t)(t1 + 1) * VV;
                if (n < nmax)     { d0[n]     = v0 + bias[n];     d1[n]     = v2 + bias[n]; }
                if (n + 1 < nmax) { d0[n + 1] = v1 + bias[n + 1]; d1[n + 1] = v3 + bias[n + 1]; }
            }
        }
}

// ---------------- persistent LSTM recurrence: all 24 steps in one launch ----------
// 16 blocks; block owns 128 permuted gate cols (= 32 hidden units). Between steps
// a global spin-barrier (g_ctr, reset by k_init each replay) orders h handoff.
// h is read via cp.async.cg (L2-coherent, bypasses L1) so no stale-L1 hazard.
__global__ __launch_bounds__(256, 1)
void mma_steps() {
    extern __shared__ char sm[];
    const int tid  = threadIdx.x;
    const int lane = tid & 31;
    const int w    = tid >> 5;
    const int wm   = w & 1, wn = w >> 1;
    const int tpar = lane & 1;

    for (int t = 0; t < TT; t++) {
        const __half* hin = (t & 1) ? g_hB : g_hA;
        __half*       hout = (t & 1) ? g_hA : g_hB;

        float acc[4][4][4];
#pragma unroll
        for (int a = 0; a < 4; a++)
#pragma unroll
            for (int b = 0; b < 4; b++)
#pragma unroll
                for (int c = 0; c < 4; c++) acc[a][b][c] = 0.0f;

        gemm_mainloop(sm, hin, 0, g_Whh, blockIdx.x * 128, acc);

#pragma unroll
        for (int mi = 0; mi < 4; mi++)
#pragma unroll
            for (int ni = 0; ni < 4; ni++) {
                int m = wm * 64 + mi * 16 + (lane >> 2);       // batch row
                int n = blockIdx.x * 128 + wn * 32 + ni * 8 + (lane & 3) * 2;  // permuted gate col
                int r = t * 128 + m;
                const float* xg = g_Xg + (size_t)r * G4;

                float c0 = acc[mi][ni][0] + xg[n];
                float c1 = acc[mi][ni][1] + xg[n + 1];
                float c2 = acc[mi][ni][2] + xg[8 * G4 + n];
                float c3 = acc[mi][ni][3] + xg[8 * G4 + n + 1];

                float e0 = __shfl_xor_sync(0xFFFFFFFFu, c0, 1);
                float e1 = __shfl_xor_sync(0xFFFFFFFFu, c1, 1);
                float e2 = __shfl_xor_sync(0xFFFFFFFFu, c2, 1);
                float e3 = __shfl_xor_sync(0xFFFFFFFFu, c3, 1);

                int   row, j = n >> 2;
                float iv, fv, gv, ov;
                if (!tpar) { row = m;     iv = c0; fv = c1; gv = e0; ov = e1; }
                else       { row = m + 8; iv = e2; fv = e3; gv = c2; ov = c3; }

                float cO = g_c[row * HH + j];
                float cN = sigf(fv) * cO + sigf(iv) * tanhf(gv);
                float hN = sigf(ov) * tanhf(cN);
                g_c[row * HH + j] = cN;

                __half hh = __float2half(hN);
                hout[row * HH + j] = hh;
                g_Hall[(size_t)(t * 128 + row) * HH + j] = hh;
            }

        if (t + 1 < TT) {
            __syncthreads();                       // block's h writes all issued
            if (tid == 0) {
                __threadfence();                   // publish h to L2
                atomicAdd(&g_ctr, 1);
                int target = 16 * (t + 1);
                while (atomicAdd(&g_ctr, 0) < target) { }
            }
            __syncthreads();                       // release whole block
        }
    }
}

// ---------------- prep kernels ----------------
__global__ void k_init(const float* __restrict__ img,
                       const float* __restrict__ bih,
                       const float* __restrict__ bhh) {
    int i = blockIdx.x * blockDim.x + threadIdx.x;
    if (i == 0) g_ctr = 0;                         // reset recurrence barrier
    if (i < BB * HH) {
        g_hA[i] = __float2half(img[i]);
        g_c[i] = 0.0f;
    }
    if (i < G4) {   // permuted bias: rp = j*4+g  <-  g*512+j
        int j = i >> 2, g = i & 3;
        g_bias[i] = bih[g * HH + j] + bhh[g * HH + j];
    }
}

__global__ void k_embed(const int* __restrict__ caps, const float* __restrict__ Wemb) {
    int idx = blockIdx.x * blockDim.x + threadIdx.x;    // over BTR*128 float4 groups
    if (idx >= BTR * 128) return;
    int e4 = idx & 127, r = idx >> 7;
    int t = r >> 7, b = r & 127;
    int tok = caps[b * TT + t];
    float4 v = make_float4(0.f, 0.f, 0.f, 0.f);
    if (tok != 0) v = *(const float4*)(Wemb + (size_t)tok * EE + e4 * 4);
    int base = r * EE + e4 * 4;
    g_X[base + 0] = __float2half(v.x);
    g_X[base + 1] = __float2half(v.y);
    g_X[base + 2] = __float2half(v.z);
    g_X[base + 3] = __float2half(v.w);
}

// permuted fp16 convert for W_ih / W_hh: dst row rp = j*4+g <- src row g*512+j
__global__ void k_split_perm(const float* __restrict__ W, __half* __restrict__ dst) {
    int idx = blockIdx.x * blockDim.x + threadIdx.x;    // over G4*128 float4 groups
    if (idx >= G4 * 128) return;
    int k4 = idx & 127, rp = idx >> 7;
    int j = rp >> 2, g = rp & 3;
    float4 v = *(const float4*)(W + (size_t)(g * HH + j) * 512 + k4 * 4);
    int base = rp * 512 + k4 * 4;
    dst[base + 0] = __float2half(v.x);
    dst[base + 1] = __float2half(v.y);
    dst[base + 2] = __float2half(v.z);
    dst[base + 3] = __float2half(v.w);
}

__global__ void k_split_out(const float* __restrict__ W) {
    int idx = blockIdx.x * blockDim.x + threadIdx.x;    // over NPAD*128 float4 groups
    if (idx >= NPAD * 128) return;
    int k4 = idx & 127, r = idx >> 7;
    float4 v = make_float4(0.f, 0.f, 0.f, 0.f);
    if (r < VV) v = *(const float4*)(W + (size_t)r * HH + k4 * 4);
    int base = r * 512 + k4 * 4;
    g_Wout[base + 0] = __float2half(v.x);
    g_Wout[base + 1] = __float2half(v.y);
    g_Wout[base + 2] = __float2half(v.z);
    g_Wout[base + 3] = __float2half(v.w);
}

__global__ void k_start(float* __restrict__ out, const int* __restrict__ clen, int extra) {
    int i = blockIdx.x * blockDim.x + threadIdx.x;
    const int n = BB * VV;
    if (i < n) {
        int b = i / VV;
        int v = i - b * VV;
        out[(size_t)b * OUTROW + v] = (v == 1) ? 1.0f : 0.0f;
    }
    if (i < extra) {
        float val = (i < BB) ? (float)(clen[i] - 1) : 0.0f;
        out[(size_t)BB * OUTROW + i] = val;
    }
}

// ---------------- launch ----------------
extern "C" void kernel_launch(void* const* d_in, const int* in_sizes, int n_in,
                              void* d_out, int out_size) {
    const float* images = (const float*)d_in[0];
    const int*   caps   = (const int*)  d_in[1];
    const int*   clen   = (const int*)  d_in[2];
    const float* Wemb   = (const float*)d_in[3];
    const float* Wih    = (const float*)d_in[4];
    const float* Whh    = (const float*)d_in[5];
    const float* bih    = (const float*)d_in[6];
    const float* bhh    = (const float*)d_in[7];
    const float* Wout   = (const float*)d_in[8];
    const float* bout   = (const float*)d_in[9];
    float* out = (float*)d_out;

    cudaFuncSetAttribute(mma_gemm,  cudaFuncAttributeMaxDynamicSharedMemorySize, SMEM_DYN);
    cudaFuncSetAttribute(mma_steps, cudaFuncAttributeMaxDynamicSharedMemorySize, SMEM_DYN);

    __half *pX, *pWih, *pWhh, *pWout, *pH;
    float *pbias, *pXg;
    cudaGetSymbolAddress((void**)&pX,    g_X);
    cudaGetSymbolAddress((void**)&pWih,  g_Wih);
    cudaGetSymbolAddress((void**)&pWhh,  g_Whh);
    cudaGetSymbolAddress((void**)&pWout, g_Wout);
    cudaGetSymbolAddress((void**)&pH,    g_Hall);
    cudaGetSymbolAddress((void**)&pbias, g_bias);
    cudaGetSymbolAddress((void**)&pXg,   g_Xg);

    // 1. init: h0 fp16, c0, permuted bias, barrier reset
    k_init<<<(BB * HH + 255) / 256, 256>>>(images, bih, bhh);

    // 2. embedding -> fp16
    k_embed<<<(BTR * 128 + 255) / 256, 256>>>(caps, Wemb);

    // 3. weight converts
    k_split_perm<<<(G4 * 128 + 255) / 256, 256>>>(Wih, pWih);
    k_split_perm<<<(G4 * 128 + 255) / 256, 256>>>(Whh, pWhh);
    k_split_out <<<(NPAD * 128 + 255) / 256, 256>>>(Wout);

    // 4. Xg = X @ Wih'^T + bias'   [3072 x 2048]
    {
        dim3 grid(G4 / 128, BTR / 128);
        mma_gemm<<<grid, 256, SMEM_DYN>>>(pX, pWih, pbias, pXg, G4, G4, 0);
    }

    // 5. recurrence: one persistent kernel, 24 steps, internal global barrier
    mma_steps<<<16, 256, SMEM_DYN>>>();

    // 6. logits = H_all @ Wout^T + b_out -> scatter into d_out
    {
        dim3 grid(NPAD / 128, BTR / 128);
        mma_gemm<<<grid, 256, SMEM_DYN>>>(pH, pWout, bout, out, VV, VV, 1);
    }

    // 7. t=0 one-hot rows + optional length tail
    {
        int extra = out_size - BB * OUTROW;
        if (extra < 0) extra = 0;
        k_start<<<(BB * VV + 255) / 256, 256>>>(out, clen, extra);
    }
}

// round 13
// speedup vs baseline: 2.9763x; 1.6277x over previous
#include <cuda_runtime.h>
#include <cuda_fp16.h>
#include <math.h>
#include <stdint.h>

#define BB   128
#define TT   24
#define EE   512
#define HH   512
#define VV   10000
#define G4   2048
#define BTR  3072
#define OUTROW 250000
#define NPAD 10112          // 79 * 128  (padded vocab rows)
#define RNN_BLOCKS 32

// ---------------- device scratch (no allocations allowed) ----------------
__device__ __half g_X   [BTR * EE];        // embedded captions (fp16)
__device__ __half g_Wih [G4 * EE];         // permuted W_ih (fp16)
__device__ __half g_Whh [G4 * HH];         // permuted W_hh (fp16)
__device__ __half g_Wout[NPAD * HH];       // padded W_out (fp16)
__device__ __half g_Hall[BTR * HH];        // all hidden states (fp16)
__device__ __half g_hA  [BB * HH];
__device__ __half g_hB  [BB * HH];
__device__ float  g_c   [BB * HH];
__device__ float  g_bias[G4];              // permuted b_ih+b_hh
__device__ float  g_Xg  [BTR * G4];        // input gates (permuted cols)
__device__ int    g_ctr;                   // recurrence spin-barrier counter

// ---------------- small helpers ----------------
__device__ __forceinline__ float sigf(float x) { return 1.0f / (1.0f + expf(-x)); }

__device__ __forceinline__ uint32_t smem_to_u32(const void* p) {
    uint32_t a;
    asm("{ .reg .u64 t; cvta.to.shared.u64 t, %1; cvt.u32.u64 %0, t; }" : "=r"(a) : "l"(p));
    return a;
}

// ---------------- warp-level tensor ops (sm_80+ PTX; legal on plain sm_103) ----
__device__ __forceinline__ void ldsm_x4(uint32_t* r, uint32_t addr) {
    asm volatile("ldmatrix.sync.aligned.m8n8.x4.shared.b16 {%0,%1,%2,%3}, [%4];"
                 : "=r"(r[0]), "=r"(r[1]), "=r"(r[2]), "=r"(r[3]) : "r"(addr));
}

__device__ __forceinline__ void mma_f16(float* c, const uint32_t* a, const uint32_t* b) {
    asm volatile(
        "mma.sync.aligned.m16n8k16.row.col.f32.f16.f16.f32 "
        "{%0,%1,%2,%3}, {%4,%5,%6,%7}, {%8,%9}, {%0,%1,%2,%3};"
        : "+f"(c[0]), "+f"(c[1]), "+f"(c[2]), "+f"(c[3])
        : "r"(a[0]), "r"(a[1]), "r"(a[2]), "r"(a[3]), "r"(b[0]), "r"(b[1]));
}

// ---------------- cp.async (sm_80+ PTX) ----------------
__device__ __forceinline__ void cp_async16(uint32_t dst, const void* src) {
    asm volatile("cp.async.cg.shared.global [%0], [%1], 16;" :: "r"(dst), "l"(src));
}
#define CP_COMMIT() asm volatile("cp.async.commit_group;" ::: "memory")
// Wait helper: final K-tile's data is the NEWEST committed group, so the last
// iteration must drain everything (wait_group 0); earlier iterations may leave
// the newest group (the next tile's prefetch) in flight (wait_group 1).
__device__ __forceinline__ void cp_wait(bool last) {
    if (last) asm volatile("cp.async.wait_group 0;" ::: "memory");
    else      asm volatile("cp.async.wait_group 1;" ::: "memory");
}

// ---------------- smem layout (GEMM kernels) ----------------
// Plane = 128 rows x 64 fp16 k, rows padded to 144B -> 18432 B.
// Row stride 144B = 36 words; 36 mod 32 = 4 => ldmatrix phases conflict-free.
#define TILE_B   (128 * 144)
#define SM_A     0
#define SM_B     (1 * TILE_B)
#define STAGE_B  (2 * TILE_B)       // 36864
#define SMEM_DYN (2 * STAGE_B)      // 73728

// Async-load one 128x64 fp16 tile (gmem ld = 512) into padded smem rows.
__device__ __forceinline__ void load_tile_async(uint32_t dst, const __half* src,
                                                int row0, int k0, int tid) {
#pragma unroll
    for (int i = 0; i < 4; i++) {
        int e  = tid + i * 256;           // 0..1023 groups of 8 fp16
        int r  = e >> 3;                  // 0..127
        int k8 = (e & 7) << 3;            // 0..56
        cp_async16(dst + r * 144 + k8 * 2,
                   src + (size_t)(row0 + r) * 512 + k0 + k8);
    }
}

__device__ __forceinline__ void load_stage(uint32_t stage,
        const __half* A, int arow0, const __half* Bm, int brow0,
        int k0, int tid) {
    load_tile_async(stage + SM_A, A, arow0, k0, tid);
    load_tile_async(stage + SM_B, Bm, brow0, k0, tid);
    CP_COMMIT();
}

// ---------------- GEMM mainloop: 2-stage pipeline -----------------------------
// acc[mi][ni][4] += A[128xK] @ B[128xK]^T   (fp16 inputs, fp32 accumulate)
// Warp grid: 8 warps = 2(m) x 4(n); warp tile 64m x 32n; K = 512, K-tile 64.
__device__ __forceinline__ void gemm_mainloop(char* sm,
        const __half* A, int arow0, const __half* Bm, int brow0,
        float acc[4][4][4]) {
    const int tid  = threadIdx.x;
    const int lane = tid & 31;
    const int w    = tid >> 5;
    const int wm   = w & 1;
    const int wn   = w >> 1;
    const uint32_t sb = smem_to_u32(sm);

    const int lrow = lane & 15;
    const int lcol = (lane >> 4) * 16;    // byte offset within 32B k16 chunk

    load_stage(sb,           A, arow0, Bm, brow0, 0,  tid);
    load_stage(sb + STAGE_B, A, arow0, Bm, brow0, 64, tid);

    for (int kt = 0; kt < 8; kt++) {
        const uint32_t cur = sb + (kt & 1) * STAGE_B;
        cp_wait(kt == 7);            // stage kt arrived (kt<7: kt+1 may be in flight)
        __syncthreads();

#pragma unroll
        for (int kc = 0; kc < 4; kc++) {
            uint32_t ah[4][4], bh[4][2];
#pragma unroll
            for (int mi = 0; mi < 4; mi++) {
                uint32_t a = cur + SM_A + (wm * 64 + mi * 16 + lrow) * 144 + kc * 32 + lcol;
                ldsm_x4(ah[mi], a);
            }
#pragma unroll
            for (int n2 = 0; n2 < 2; n2++) {
                uint32_t r0[4];
                uint32_t b = cur + SM_B + (wn * 32 + n2 * 16 + lrow) * 144 + kc * 32 + lcol;
                ldsm_x4(r0, b);
                bh[n2 * 2 + 0][0] = r0[0]; bh[n2 * 2 + 0][1] = r0[2];
                bh[n2 * 2 + 1][0] = r0[1]; bh[n2 * 2 + 1][1] = r0[3];
            }
#pragma unroll
            for (int mi = 0; mi < 4; mi++)
#pragma unroll
                for (int ni = 0; ni < 4; ni++)
                    mma_f16(acc[mi][ni], ah[mi], bh[ni]);
        }
        __syncthreads();             // all warps done reading `cur`
        if (kt + 2 < 8)
            load_stage(cur, A, arow0, Bm, brow0, (kt + 2) * 64, tid);
    }
}

// ---------------- generic GEMM kernel (mode 0 plain, 1 logits scatter) ----------------
__global__ __launch_bounds__(256, 2)
void mma_gemm(const __half* __restrict__ A, const __half* __restrict__ Bm,
              const float* __restrict__ bias, float* __restrict__ Cout,
              int ldc, int nmax, int mode) {
    extern __shared__ char sm[];
    float acc[4][4][4];
#pragma unroll
    for (int a = 0; a < 4; a++)
#pragma unroll
        for (int b = 0; b < 4; b++)
#pragma unroll
            for (int c = 0; c < 4; c++) acc[a][b][c] = 0.0f;

    gemm_mainloop(sm, A, blockIdx.y * 128, Bm, blockIdx.x * 128, acc);

    const int lane = threadIdx.x & 31;
    const int w    = threadIdx.x >> 5;
    const int wm   = w & 1, wn = w >> 1;

#pragma unroll
    for (int mi = 0; mi < 4; mi++)
#pragma unroll
        for (int ni = 0; ni < 4; ni++) {
            int m = blockIdx.y * 128 + wm * 64 + mi * 16 + (lane >> 2);
            int n = blockIdx.x * 128 + wn * 32 + ni * 8 + (lane & 3) * 2;
            float v0 = acc[mi][ni][0];
            float v1 = acc[mi][ni][1];
            float v2 = acc[mi][ni][2];
            float v3 = acc[mi][ni][3];
            if (mode == 0) {
                Cout[(size_t)m * ldc + n]           = v0 + bias[n];
                Cout[(size_t)m * ldc + n + 1]       = v1 + bias[n + 1];
                Cout[(size_t)(m + 8) * ldc + n]     = v2 + bias[n];
                Cout[(size_t)(m + 8) * ldc + n + 1] = v3 + bias[n + 1];
            } else {
                int t0 = m >> 7, b0 = m & 127;
                int t1 = (m + 8) >> 7, b1 = (m + 8) & 127;
                float* d0 = Cout + (size_t)b0 * OUTROW + (size_t)(t0 + 1) * VV;
                float* d1 = Cout + (size_t)b1 * OUTROW + (size_t)(t1 + 1) * VV;
                if (n < nmax)     { d0[n]     = v0 + bias[n];     d1[n]     = v2 + bias[n]; }
                if (n + 1 < nmax) { d0[n + 1] = v1 + bias[n + 1]; d1[n + 1] = v3 + bias[n + 1]; }
            }
        }
}

// ---------------- persistent LSTM recurrence --------------------------------
// 32 blocks; block owns 64 permuted gate cols (16 hidden units) for ALL 128
// batch rows. Whh slice (64 x 512 fp16) is loaded into smem ONCE and stays
// resident for all 24 steps. Per step only h (128x512 fp16) is streamed via
// cp.async (L1-bypassing => coherent with other blocks' writes after the
// global spin barrier).
// Warp grid: 8 warps = 2(m) x 4(n); warp tile 64m x 16n.
// smem: W rows padded to 1040B (260 words % 32 == 4: ldmatrix conflict-free).
#define RW_ROW   1040
#define RSM_W    0
#define RSM_H0   (64 * RW_ROW)                 // 66560
#define RSM_H1   (RSM_H0 + TILE_B)             // +18432
#define SMEM_RNN (RSM_H1 + TILE_B)             // 103424

__global__ __launch_bounds__(256, 1)
void mma_steps() {
    extern __shared__ char sm[];
    const uint32_t sb = smem_to_u32(sm);
    const int tid  = threadIdx.x;
    const int lane = tid & 31;
    const int w    = tid >> 5;
    const int wm   = w & 1, wn = w >> 1;    // wm 0..1, wn 0..3
    const int tpar = lane & 1;
    const int jb   = blockIdx.x;            // 0..31

    const int lrow = lane & 15;
    const int lcol = (lane >> 4) * 16;

    // ---- load persistent Whh slice: 64 rows x 512 cols (4096 8-elt groups) ----
#pragma unroll
    for (int i = 0; i < 16; i++) {
        int e  = tid + i * 256;
        int r  = e >> 6;                   // 0..63
        int k8 = (e & 63) << 3;            // 0..504
        cp_async16(sb + RSM_W + r * RW_ROW + k8 * 2,
                   g_Whh + (size_t)(jb * 64 + r) * 512 + k8);
    }
    CP_COMMIT();

    for (int t = 0; t < TT; t++) {
        const __half* hin  = (t & 1) ? g_hB : g_hA;
        __half*       hout = (t & 1) ? g_hA : g_hB;

        // prologue: h tiles 0 and 1
        load_tile_async(sb + RSM_H0, hin, 0, 0, tid);  CP_COMMIT();
        load_tile_async(sb + RSM_H1, hin, 0, 64, tid); CP_COMMIT();

        float acc[4][2][4];
#pragma unroll
        for (int a = 0; a < 4; a++)
#pragma unroll
            for (int b = 0; b < 2; b++)
#pragma unroll
                for (int c = 0; c < 4; c++) acc[a][b][c] = 0.0f;

        for (int kt = 0; kt < 8; kt++) {
            const uint32_t curH = sb + ((kt & 1) ? RSM_H1 : RSM_H0);
            cp_wait(kt == 7);
            __syncthreads();

#pragma unroll
            for (int kc = 0; kc < 4; kc++) {
                uint32_t ah[4][4], bh[2][2];
#pragma unroll
                for (int mi = 0; mi < 4; mi++) {
                    uint32_t a = curH + (wm * 64 + mi * 16 + lrow) * 144 + kc * 32 + lcol;
                    ldsm_x4(ah[mi], a);
                }
                {
                    uint32_t r0[4];
                    uint32_t b = sb + RSM_W + (wn * 16 + lrow) * RW_ROW
                               + kt * 128 + kc * 32 + lcol;
                    ldsm_x4(r0, b);
                    bh[0][0] = r0[0]; bh[0][1] = r0[2];
                    bh[1][0] = r0[1]; bh[1][1] = r0[3];
                }
#pragma unroll
                for (int mi = 0; mi < 4; mi++)
#pragma unroll
                    for (int ni = 0; ni < 2; ni++)
                        mma_f16(acc[mi][ni], ah[mi], bh[ni]);
            }
            __syncthreads();
            if (kt + 2 < 8) {
                load_tile_async(curH, hin, 0, (kt + 2) * 64, tid);
                CP_COMMIT();
            }
        }

        // ---- cell epilogue ----
#pragma unroll
        for (int mi = 0; mi < 4; mi++)
#pragma unroll
            for (int ni = 0; ni < 2; ni++) {
                int m = wm * 64 + mi * 16 + (lane >> 2);               // batch row
                int n = jb * 64 + wn * 16 + ni * 8 + (lane & 3) * 2;   // permuted gate col
                int r = t * 128 + m;
                const float* xg = g_Xg + (size_t)r * G4;

                float c0 = acc[mi][ni][0] + xg[n];
                float c1 = acc[mi][ni][1] + xg[n + 1];
                float c2 = acc[mi][ni][2] + xg[8 * G4 + n];
                float c3 = acc[mi][ni][3] + xg[8 * G4 + n + 1];

                float e0 = __shfl_xor_sync(0xFFFFFFFFu, c0, 1);
                float e1 = __shfl_xor_sync(0xFFFFFFFFu, c1, 1);
                float e2 = __shfl_xor_sync(0xFFFFFFFFu, c2, 1);
                float e3 = __shfl_xor_sync(0xFFFFFFFFu, c3, 1);

                int   row, j = n >> 2;
                float iv, fv, gv, ov;
                if (!tpar) { row = m;     iv = c0; fv = c1; gv = e0; ov = e1; }
                else       { row = m + 8; iv = e2; fv = e3; gv = c2; ov = c3; }

                float cO = g_c[row * HH + j];
                float cN = sigf(fv) * cO + sigf(iv) * tanhf(gv);
                float hN = sigf(ov) * tanhf(cN);
                g_c[row * HH + j] = cN;

                __half hh = __float2half(hN);
                hout[row * HH + j] = hh;
                g_Hall[(size_t)(t * 128 + row) * HH + j] = hh;
            }

        if (t + 1 < TT) {
            __syncthreads();
            if (tid == 0) {
                __threadfence();
                atomicAdd(&g_ctr, 1);
                int target = RNN_BLOCKS * (t + 1);
                while (atomicAdd(&g_ctr, 0) < target) { }
            }
            __syncthreads();
        }
    }
}

// ---------------- prep kernels ----------------
__global__ void k_init(const float* __restrict__ img,
                       const float* __restrict__ bih,
                       const float* __restrict__ bhh) {
    int i = blockIdx.x * blockDim.x + threadIdx.x;
    if (i == 0) g_ctr = 0;                         // reset recurrence barrier
    if (i < BB * HH) {
        g_hA[i] = __float2half(img[i]);
        g_c[i] = 0.0f;
    }
    if (i < G4) {   // permuted bias: rp = j*4+g  <-  g*512+j
        int j = i >> 2, g = i & 3;
        g_bias[i] = bih[g * HH + j] + bhh[g * HH + j];
    }
}

__global__ void k_embed(const int* __restrict__ caps, const float* __restrict__ Wemb) {
    int idx = blockIdx.x * blockDim.x + threadIdx.x;    // over BTR*128 float4 groups
    if (idx >= BTR * 128) return;
    int e4 = idx & 127, r = idx >> 7;
    int t = r >> 7, b = r & 127;
    int tok = caps[b * TT + t];
    float4 v = make_float4(0.f, 0.f, 0.f, 0.f);
    if (tok != 0) v = *(const float4*)(Wemb + (size_t)tok * EE + e4 * 4);
    int base = r * EE + e4 * 4;
    g_X[base + 0] = __float2half(v.x);
    g_X[base + 1] = __float2half(v.y);
    g_X[base + 2] = __float2half(v.z);
    g_X[base + 3] = __float2half(v.w);
}

// permuted fp16 convert for W_ih / W_hh: dst row rp = j*4+g <- src row g*512+j
__global__ void k_split_perm(const float* __restrict__ W, __half* __restrict__ dst) {
    int idx = blockIdx.x * blockDim.x + threadIdx.x;    // over G4*128 float4 groups
    if (idx >= G4 * 128) return;
    int k4 = idx & 127, rp = idx >> 7;
    int j = rp >> 2, g = rp & 3;
    float4 v = *(const float4*)(W + (size_t)(g * HH + j) * 512 + k4 * 4);
    int base = rp * 512 + k4 * 4;
    dst[base + 0] = __float2half(v.x);
    dst[base + 1] = __float2half(v.y);
    dst[base + 2] = __float2half(v.z);
    dst[base + 3] = __float2half(v.w);
}

__global__ void k_split_out(const float* __restrict__ W) {
    int idx = blockIdx.x * blockDim.x + threadIdx.x;    // over NPAD*128 float4 groups
    if (idx >= NPAD * 128) return;
    int k4 = idx & 127, r = idx >> 7;
    float4 v = make_float4(0.f, 0.f, 0.f, 0.f);
    if (r < VV) v = *(const float4*)(W + (size_t)r * HH + k4 * 4);
    int base = r * 512 + k4 * 4;
    g_Wout[base + 0] = __float2half(v.x);
    g_Wout[base + 1] = __float2half(v.y);
    g_Wout[base + 2] = __float2half(v.z);
    g_Wout[base + 3] = __float2half(v.w);
}

__global__ void k_start(float* __restrict__ out, const int* __restrict__ clen, int extra) {
    int i = blockIdx.x * blockDim.x + threadIdx.x;
    const int n = BB * VV;
    if (i < n) {
        int b = i / VV;
        int v = i - b * VV;
        out[(size_t)b * OUTROW + v] = (v == 1) ? 1.0f : 0.0f;
    }
    if (i < extra) {
        float val = (i < BB) ? (float)(clen[i] - 1) : 0.0f;
        out[(size_t)BB * OUTROW + i] = val;
    }
}

// ---------------- launch ----------------
extern "C" void kernel_launch(void* const* d_in, const int* in_sizes, int n_in,
                              void* d_out, int out_size) {
    const float* images = (const float*)d_in[0];
    const int*   caps   = (const int*)  d_in[1];
    const int*   clen   = (const int*)  d_in[2];
    const float* Wemb   = (const float*)d_in[3];
    const float* Wih    = (const float*)d_in[4];
    const float* Whh    = (const float*)d_in[5];
    const float* bih    = (const float*)d_in[6];
    const float* bhh    = (const float*)d_in[7];
    const float* Wout   = (const float*)d_in[8];
    const float* bout   = (const float*)d_in[9];
    float* out = (float*)d_out;

    cudaFuncSetAttribute(mma_gemm,  cudaFuncAttributeMaxDynamicSharedMemorySize, SMEM_DYN);
    cudaFuncSetAttribute(mma_steps, cudaFuncAttributeMaxDynamicSharedMemorySize, SMEM_RNN);

    __half *pX, *pWih, *pWhh, *pWout, *pH;
    float *pbias, *pXg;
    cudaGetSymbolAddress((void**)&pX,    g_X);
    cudaGetSymbolAddress((void**)&pWih,  g_Wih);
    cudaGetSymbolAddress((void**)&pWhh,  g_Whh);
    cudaGetSymbolAddress((void**)&pWout, g_Wout);
    cudaGetSymbolAddress((void**)&pH,    g_Hall);
    cudaGetSymbolAddress((void**)&pbias, g_bias);
    cudaGetSymbolAddress((void**)&pXg,   g_Xg);

    // 1. init: h0 fp16, c0, permuted bias, barrier reset
    k_init<<<(BB * HH + 255) / 256, 256>>>(images, bih, bhh);

    // 2. embedding -> fp16
    k_embed<<<(BTR * 128 + 255) / 256, 256>>>(caps, Wemb);

    // 3. weight converts
    k_split_perm<<<(G4 * 128 + 255) / 256, 256>>>(Wih, pWih);
    k_split_perm<<<(G4 * 128 + 255) / 256, 256>>>(Whh, pWhh);
    k_split_out <<<(NPAD * 128 + 255) / 256, 256>>>(Wout);

    // 4. Xg = X @ Wih'^T + bias'   [3072 x 2048]
    {
        dim3 grid(G4 / 128, BTR / 128);
        mma_gemm<<<grid, 256, SMEM_DYN>>>(pX, pWih, pbias, pXg, G4, G4, 0);
    }

    // 5. recurrence: one persistent kernel, 32 blocks, smem-resident Whh
    mma_steps<<<RNN_BLOCKS, 256, SMEM_RNN>>>();

    // 6. logits = H_all @ Wout^T + b_out -> scatter into d_out
    {
        dim3 grid(NPAD / 128, BTR / 128);
        mma_gemm<<<grid, 256, SMEM_DYN>>>(pH, pWout, bout, out, VV, VV, 1);
    }

    // 7. t=0 one-hot rows + optional length tail
    {
        int extra = out_size - BB * OUTROW;
        if (extra < 0) extra = 0;
        k_start<<<(BB * VV + 255) / 256, 256>>>(out, clen, extra);
    }
}

// round 14
// speedup vs baseline: 3.3325x; 1.1197x over previous
#include <cuda_runtime.h>
#include <cuda_fp16.h>
#include <math.h>
#include <stdint.h>

#define BB   128
#define TT   24
#define EE   512
#define HH   512
#define VV   10000
#define G4   2048
#define BTR  3072
#define OUTROW 250000
#define NPAD 10112          // 79 * 128  (padded vocab rows)
#define RNN_BLOCKS 32
#define NTILES_N 79         // logits n-tiles per time step
#define NTILES   (TT * NTILES_N)   // 1896

// ---------------- device scratch (no allocations allowed) ----------------
__device__ __half g_X   [BTR * EE];        // embedded captions (fp16)
__device__ __half g_Wih [G4 * EE];         // permuted W_ih (fp16)
__device__ __half g_Whh [G4 * HH];         // permuted W_hh (fp16)
__device__ __half g_Wout[NPAD * HH];       // padded W_out (fp16)
__device__ __half g_Hall[BTR * HH];        // all hidden states (fp16)
__device__ __half g_hA  [BB * HH];
__device__ __half g_hB  [BB * HH];
__device__ float  g_c   [BB * HH];
__device__ float  g_bias[G4];              // permuted b_ih+b_hh
__device__ float  g_Xg  [BTR * G4];        // input gates (permuted cols)
__device__ int    g_ctr;                   // recurrence step counter (32 arrivals/step)
__device__ int    g_tile;                  // logits tile work queue

// ---------------- small helpers ----------------
__device__ __forceinline__ float sigf(float x) { return 1.0f / (1.0f + expf(-x)); }

__device__ __forceinline__ uint32_t smem_to_u32(const void* p) {
    uint32_t a;
    asm("{ .reg .u64 t; cvta.to.shared.u64 t, %1; cvt.u32.u64 %0, t; }" : "=r"(a) : "l"(p));
    return a;
}

// ---------------- warp-level tensor ops (sm_80+ PTX; legal on plain sm_103) ----
__device__ __forceinline__ void ldsm_x4(uint32_t* r, uint32_t addr) {
    asm volatile("ldmatrix.sync.aligned.m8n8.x4.shared.b16 {%0,%1,%2,%3}, [%4];"
                 : "=r"(r[0]), "=r"(r[1]), "=r"(r[2]), "=r"(r[3]) : "r"(addr));
}

__device__ __forceinline__ void mma_f16(float* c, const uint32_t* a, const uint32_t* b) {
    asm volatile(
        "mma.sync.aligned.m16n8k16.row.col.f32.f16.f16.f32 "
        "{%0,%1,%2,%3}, {%4,%5,%6,%7}, {%8,%9}, {%0,%1,%2,%3};"
        : "+f"(c[0]), "+f"(c[1]), "+f"(c[2]), "+f"(c[3])
        : "r"(a[0]), "r"(a[1]), "r"(a[2]), "r"(a[3]), "r"(b[0]), "r"(b[1]));
}

// ---------------- cp.async (sm_80+ PTX) ----------------
__device__ __forceinline__ void cp_async16(uint32_t dst, const void* src) {
    asm volatile("cp.async.cg.shared.global [%0], [%1], 16;" :: "r"(dst), "l"(src));
}
#define CP_COMMIT() asm volatile("cp.async.commit_group;" ::: "memory")
// Final K-tile's data is the NEWEST committed group -> must drain all (wait 0);
// earlier tiles may leave the next prefetch in flight (wait 1).
__device__ __forceinline__ void cp_wait(bool last) {
    if (last) asm volatile("cp.async.wait_group 0;" ::: "memory");
    else      asm volatile("cp.async.wait_group 1;" ::: "memory");
}

// ---------------- smem layout (GEMM path) ----------------
// Plane = 128 rows x 64 fp16 k, rows padded to 144B -> 18432 B.
// Row stride 144B = 36 words; 36 mod 32 = 4 => ldmatrix phases conflict-free.
#define TILE_B   (128 * 144)
#define SM_A     0
#define SM_B     (1 * TILE_B)
#define STAGE_B  (2 * TILE_B)       // 36864
#define SMEM_DYN (2 * STAGE_B)      // 73728 (standalone GEMM)

// RNN smem: persistent Whh slice + double-buffered h tiles.
#define RW_ROW   1040
#define RSM_W    0
#define RSM_H0   (64 * RW_ROW)                 // 66560
#define RSM_H1   (RSM_H0 + TILE_B)
#define SMEM_RNN (RSM_H1 + TILE_B)             // 103424 (fused kernel)

// Async-load one 128x64 fp16 tile (gmem ld = 512) into padded smem rows.
__device__ __forceinline__ void load_tile_async(uint32_t dst, const __half* src,
                                                int row0, int k0, int tid) {
#pragma unroll
    for (int i = 0; i < 4; i++) {
        int e  = tid + i * 256;           // 0..1023 groups of 8 fp16
        int r  = e >> 3;                  // 0..127
        int k8 = (e & 7) << 3;            // 0..56
        cp_async16(dst + r * 144 + k8 * 2,
                   src + (size_t)(row0 + r) * 512 + k0 + k8);
    }
}

__device__ __forceinline__ void load_stage(uint32_t stage,
        const __half* A, int arow0, const __half* Bm, int brow0,
        int k0, int tid) {
    load_tile_async(stage + SM_A, A, arow0, k0, tid);
    load_tile_async(stage + SM_B, Bm, brow0, k0, tid);
    CP_COMMIT();
}

// ---------------- GEMM mainloop: 2-stage cp.async pipeline --------------------
// acc[mi][ni][4] += A[128xK] @ B[128xK]^T   (fp16 inputs, fp32 accumulate)
// Warp grid: 8 warps = 2(m) x 4(n); warp tile 64m x 32n; K = 512, K-tile 64.
__device__ __forceinline__ void gemm_mainloop(char* sm,
        const __half* A, int arow0, const __half* Bm, int brow0,
        float acc[4][4][4]) {
    const int tid  = threadIdx.x;
    const int lane = tid & 31;
    const int w    = tid >> 5;
    const int wm   = w & 1;
    const int wn   = w >> 1;
    const uint32_t sb = smem_to_u32(sm);

    const int lrow = lane & 15;
    const int lcol = (lane >> 4) * 16;    // byte offset within 32B k16 chunk

    load_stage(sb,           A, arow0, Bm, brow0, 0,  tid);
    load_stage(sb + STAGE_B, A, arow0, Bm, brow0, 64, tid);

    for (int kt = 0; kt < 8; kt++) {
        const uint32_t cur = sb + (kt & 1) * STAGE_B;
        cp_wait(kt == 7);
        __syncthreads();

#pragma unroll
        for (int kc = 0; kc < 4; kc++) {
            uint32_t ah[4][4], bh[4][2];
#pragma unroll
            for (int mi = 0; mi < 4; mi++) {
                uint32_t a = cur + SM_A + (wm * 64 + mi * 16 + lrow) * 144 + kc * 32 + lcol;
                ldsm_x4(ah[mi], a);
            }
#pragma unroll
            for (int n2 = 0; n2 < 2; n2++) {
                uint32_t r0[4];
                uint32_t b = cur + SM_B + (wn * 32 + n2 * 16 + lrow) * 144 + kc * 32 + lcol;
                ldsm_x4(r0, b);
                bh[n2 * 2 + 0][0] = r0[0]; bh[n2 * 2 + 0][1] = r0[2];
                bh[n2 * 2 + 1][0] = r0[1]; bh[n2 * 2 + 1][1] = r0[3];
            }
#pragma unroll
            for (int mi = 0; mi < 4; mi++)
#pragma unroll
                for (int ni = 0; ni < 4; ni++)
                    mma_f16(acc[mi][ni], ah[mi], bh[ni]);
        }
        __syncthreads();
        if (kt + 2 < 8)
            load_stage(cur, A, arow0, Bm, brow0, (kt + 2) * 64, tid);
    }
}

// ---------------- standalone GEMM kernel (Xg only: mode-0 store) ----------------
__global__ __launch_bounds__(256, 2)
void mma_gemm(const __half* __restrict__ A, const __half* __restrict__ Bm,
              const float* __restrict__ bias, float* __restrict__ Cout, int ldc) {
    extern __shared__ char sm[];
    float acc[4][4][4];
#pragma unroll
    for (int a = 0; a < 4; a++)
#pragma unroll
        for (int b = 0; b < 4; b++)
#pragma unroll
            for (int c = 0; c < 4; c++) acc[a][b][c] = 0.0f;

    gemm_mainloop(sm, A, blockIdx.y * 128, Bm, blockIdx.x * 128, acc);

    const int lane = threadIdx.x & 31;
    const int w    = threadIdx.x >> 5;
    const int wm   = w & 1, wn = w >> 1;

#pragma unroll
    for (int mi = 0; mi < 4; mi++)
#pragma unroll
        for (int ni = 0; ni < 4; ni++) {
            int m = blockIdx.y * 128 + wm * 64 + mi * 16 + (lane >> 2);
            int n = blockIdx.x * 128 + wn * 32 + ni * 8 + (lane & 3) * 2;
            Cout[(size_t)m * ldc + n]           = acc[mi][ni][0] + bias[n];
            Cout[(size_t)m * ldc + n + 1]       = acc[mi][ni][1] + bias[n + 1];
            Cout[(size_t)(m + 8) * ldc + n]     = acc[mi][ni][2] + bias[n];
            Cout[(size_t)(m + 8) * ldc + n + 1] = acc[mi][ni][3] + bias[n + 1];
        }
}

// ---------------- fused persistent kernel: recurrence + logits ----------------
// Grid sized by the host so that ALL blocks are co-resident (occupancy query).
// Blocks 0..31: LSTM recurrence (R13 scheme: smem-resident Whh slice, h streamed
//   per step, global arrive counter g_ctr; now ALWAYS arrives, incl. t=23).
// All blocks (workers immediately; rnn blocks after finishing): pull logits
//   tiles (t, nb) from the g_tile atomic queue, wait for g_ctr >= 32*(t+1),
//   compute H[t] @ Wout^T + bout, scatter to out rows (t+1).
__global__ __launch_bounds__(256, 1)
void fused_rnn_logits(const float* __restrict__ bout, float* __restrict__ out) {
    extern __shared__ char sm[];
    const uint32_t sb = smem_to_u32(sm);
    const int tid  = threadIdx.x;
    const int lane = tid & 31;
    const int w    = tid >> 5;
    const int wm   = w & 1, wn = w >> 1;
    const int tpar = lane & 1;

    const int lrow = lane & 15;
    const int lcol = (lane >> 4) * 16;

    if (blockIdx.x < RNN_BLOCKS) {
        const int jb = blockIdx.x;

        // persistent Whh slice: 64 rows x 512 cols
#pragma unroll
        for (int i = 0; i < 16; i++) {
            int e  = tid + i * 256;
            int r  = e >> 6;
            int k8 = (e & 63) << 3;
            cp_async16(sb + RSM_W + r * RW_ROW + k8 * 2,
                       g_Whh + (size_t)(jb * 64 + r) * 512 + k8);
        }
        CP_COMMIT();

        for (int t = 0; t < TT; t++) {
            const __half* hin  = (t & 1) ? g_hB : g_hA;
            __half*       hout = (t & 1) ? g_hA : g_hB;

            load_tile_async(sb + RSM_H0, hin, 0, 0, tid);  CP_COMMIT();
            load_tile_async(sb + RSM_H1, hin, 0, 64, tid); CP_COMMIT();

            float acc[4][2][4];
#pragma unroll
            for (int a = 0; a < 4; a++)
#pragma unroll
                for (int b = 0; b < 2; b++)
#pragma unroll
                    for (int c = 0; c < 4; c++) acc[a][b][c] = 0.0f;

            for (int kt = 0; kt < 8; kt++) {
                const uint32_t curH = sb + ((kt & 1) ? RSM_H1 : RSM_H0);
                cp_wait(kt == 7);
                __syncthreads();

#pragma unroll
                for (int kc = 0; kc < 4; kc++) {
                    uint32_t ah[4][4], bh[2][2];
#pragma unroll
                    for (int mi = 0; mi < 4; mi++) {
                        uint32_t a = curH + (wm * 64 + mi * 16 + lrow) * 144 + kc * 32 + lcol;
                        ldsm_x4(ah[mi], a);
                    }
                    {
                        uint32_t r0[4];
                        uint32_t b = sb + RSM_W + (wn * 16 + lrow) * RW_ROW
                                   + kt * 128 + kc * 32 + lcol;
                        ldsm_x4(r0, b);
                        bh[0][0] = r0[0]; bh[0][1] = r0[2];
                        bh[1][0] = r0[1]; bh[1][1] = r0[3];
                    }
#pragma unroll
                    for (int mi = 0; mi < 4; mi++)
#pragma unroll
                        for (int ni = 0; ni < 2; ni++)
                            mma_f16(acc[mi][ni], ah[mi], bh[ni]);
                }
                __syncthreads();
                if (kt + 2 < 8) {
                    load_tile_async(curH, hin, 0, (kt + 2) * 64, tid);
                    CP_COMMIT();
                }
            }

            // cell epilogue
#pragma unroll
            for (int mi = 0; mi < 4; mi++)
#pragma unroll
                for (int ni = 0; ni < 2; ni++) {
                    int m = wm * 64 + mi * 16 + (lane >> 2);
                    int n = jb * 64 + wn * 16 + ni * 8 + (lane & 3) * 2;
                    int r = t * 128 + m;
                    const float* xg = g_Xg + (size_t)r * G4;

                    float c0 = acc[mi][ni][0] + xg[n];
                    float c1 = acc[mi][ni][1] + xg[n + 1];
                    float c2 = acc[mi][ni][2] + xg[8 * G4 + n];
                    float c3 = acc[mi][ni][3] + xg[8 * G4 + n + 1];

                    float e0 = __shfl_xor_sync(0xFFFFFFFFu, c0, 1);
                    float e1 = __shfl_xor_sync(0xFFFFFFFFu, c1, 1);
                    float e2 = __shfl_xor_sync(0xFFFFFFFFu, c2, 1);
                    float e3 = __shfl_xor_sync(0xFFFFFFFFu, c3, 1);

                    int   row, j = n >> 2;
                    float iv, fv, gv, ov;
                    if (!tpar) { row = m;     iv = c0; fv = c1; gv = e0; ov = e1; }
                    else       { row = m + 8; iv = e2; fv = e3; gv = c2; ov = c3; }

                    float cO = g_c[row * HH + j];
                    float cN = sigf(fv) * cO + sigf(iv) * tanhf(gv);
                    float hN = sigf(ov) * tanhf(cN);
                    g_c[row * HH + j] = cN;

                    __half hh = __float2half(hN);
                    hout[row * HH + j] = hh;
                    g_Hall[(size_t)(t * 128 + row) * HH + j] = hh;
                }

            // arrive (always — workers need g_ctr to reach 32*TT); spin only
            // if another step follows.
            __syncthreads();
            if (tid == 0) {
                __threadfence();
                atomicAdd(&g_ctr, 1);
                if (t + 1 < TT) {
                    int target = RNN_BLOCKS * (t + 1);
                    while (atomicAdd(&g_ctr, 0) < target) { }
                }
            }
            __syncthreads();
        }
    }

    // ---------------- logits worker loop (all blocks) ----------------
    __shared__ int s_q;
    for (;;) {
        __syncthreads();
        if (tid == 0) s_q = atomicAdd(&g_tile, 1);
        __syncthreads();
        int q = s_q;
        if (q >= NTILES) break;
        int t  = q / NTILES_N;
        int nb = q - t * NTILES_N;

        // wait until step t's hidden states are published
        if (tid == 0) {
            int target = RNN_BLOCKS * (t + 1);
            while (atomicAdd(&g_ctr, 0) < target) __nanosleep(64);
            __threadfence();
        }
        __syncthreads();

        float acc[4][4][4];
#pragma unroll
        for (int a = 0; a < 4; a++)
#pragma unroll
            for (int b = 0; b < 4; b++)
#pragma unroll
                for (int c = 0; c < 4; c++) acc[a][b][c] = 0.0f;

        gemm_mainloop(sm, g_Hall, t * 128, g_Wout, nb * 128, acc);

        // epilogue: scatter into out rows for time t+1
#pragma unroll
        for (int mi = 0; mi < 4; mi++)
#pragma unroll
            for (int ni = 0; ni < 4; ni++) {
                int b0 = wm * 64 + mi * 16 + (lane >> 2);   // batch row
                int n  = nb * 128 + wn * 32 + ni * 8 + (lane & 3) * 2;
                float* d0 = out + (size_t)b0 * OUTROW + (size_t)(t + 1) * VV;
                float* d1 = out + (size_t)(b0 + 8) * OUTROW + (size_t)(t + 1) * VV;
                if (n < VV) {
                    d0[n] = acc[mi][ni][0] + bout[n];
                    d1[n] = acc[mi][ni][2] + bout[n];
                }
                if (n + 1 < VV) {
                    d0[n + 1] = acc[mi][ni][1] + bout[n + 1];
                    d1[n + 1] = acc[mi][ni][3] + bout[n + 1];
                }
            }
    }
}

// ---------------- prep kernels ----------------
__global__ void k_init(const float* __restrict__ img,
                       const float* __restrict__ bih,
                       const float* __restrict__ bhh) {
    int i = blockIdx.x * blockDim.x + threadIdx.x;
    if (i == 0) { g_ctr = 0; g_tile = 0; }         // reset counters each replay
    if (i < BB * HH) {
        g_hA[i] = __float2half(img[i]);
        g_c[i] = 0.0f;
    }
    if (i < G4) {   // permuted bias: rp = j*4+g  <-  g*512+j
        int j = i >> 2, g = i & 3;
        g_bias[i] = bih[g * HH + j] + bhh[g * HH + j];
    }
}

__global__ void k_embed(const int* __restrict__ caps, const float* __restrict__ Wemb) {
    int idx = blockIdx.x * blockDim.x + threadIdx.x;    // over BTR*128 float4 groups
    if (idx >= BTR * 128) return;
    int e4 = idx & 127, r = idx >> 7;
    int t = r >> 7, b = r & 127;
    int tok = caps[b * TT + t];
    float4 v = make_float4(0.f, 0.f, 0.f, 0.f);
    if (tok != 0) v = *(const float4*)(Wemb + (size_t)tok * EE + e4 * 4);
    int base = r * EE + e4 * 4;
    g_X[base + 0] = __float2half(v.x);
    g_X[base + 1] = __float2half(v.y);
    g_X[base + 2] = __float2half(v.z);
    g_X[base + 3] = __float2half(v.w);
}

// permuted fp16 convert for W_ih / W_hh: dst row rp = j*4+g <- src row g*512+j
__global__ void k_split_perm(const float* __restrict__ W, __half* __restrict__ dst) {
    int idx = blockIdx.x * blockDim.x + threadIdx.x;    // over G4*128 float4 groups
    if (idx >= G4 * 128) return;
    int k4 = idx & 127, rp = idx >> 7;
    int j = rp >> 2, g = rp & 3;
    float4 v = *(const float4*)(W + (size_t)(g * HH + j) * 512 + k4 * 4);
    int base = rp * 512 + k4 * 4;
    dst[base + 0] = __float2half(v.x);
    dst[base + 1] = __float2half(v.y);
    dst[base + 2] = __float2half(v.z);
    dst[base + 3] = __float2half(v.w);
}

__global__ void k_split_out(const float* __restrict__ W) {
    int idx = blockIdx.x * blockDim.x + threadIdx.x;    // over NPAD*128 float4 groups
    if (idx >= NPAD * 128) return;
    int k4 = idx & 127, r = idx >> 7;
    float4 v = make_float4(0.f, 0.f, 0.f, 0.f);
    if (r < VV) v = *(const float4*)(W + (size_t)r * HH + k4 * 4);
    int base = r * 512 + k4 * 4;
    g_Wout[base + 0] = __float2half(v.x);
    g_Wout[base + 1] = __float2half(v.y);
    g_Wout[base + 2] = __float2half(v.z);
    g_Wout[base + 3] = __float2half(v.w);
}

__global__ void k_start(float* __restrict__ out, const int* __restrict__ clen, int extra) {
    int i = blockIdx.x * blockDim.x + threadIdx.x;
    const int n = BB * VV;
    if (i < n) {
        int b = i / VV;
        int v = i - b * VV;
        out[(size_t)b * OUTROW + v] = (v == 1) ? 1.0f : 0.0f;
    }
    if (i < extra) {
        float val = (i < BB) ? (float)(clen[i] - 1) : 0.0f;
        out[(size_t)BB * OUTROW + i] = val;
    }
}

// ---------------- launch ----------------
extern "C" void kernel_launch(void* const* d_in, const int* in_sizes, int n_in,
                              void* d_out, int out_size) {
    const float* images = (const float*)d_in[0];
    const int*   caps   = (const int*)  d_in[1];
    const int*   clen   = (const int*)  d_in[2];
    const float* Wemb   = (const float*)d_in[3];
    const float* Wih    = (const float*)d_in[4];
    const float* Whh    = (const float*)d_in[5];
    const float* bih    = (const float*)d_in[6];
    const float* bhh    = (const float*)d_in[7];
    const float* Wout   = (const float*)d_in[8];
    const float* bout   = (const float*)d_in[9];
    float* out = (float*)d_out;

    cudaFuncSetAttribute(mma_gemm,         cudaFuncAttributeMaxDynamicSharedMemorySize, SMEM_DYN);
    cudaFuncSetAttribute(fused_rnn_logits, cudaFuncAttributeMaxDynamicSharedMemorySize, SMEM_RNN);

    __half *pX, *pWih, *pWhh;
    float *pbias, *pXg;
    cudaGetSymbolAddress((void**)&pX,    g_X);
    cudaGetSymbolAddress((void**)&pWih,  g_Wih);
    cudaGetSymbolAddress((void**)&pWhh,  g_Whh);
    cudaGetSymbolAddress((void**)&pbias, g_bias);
    cudaGetSymbolAddress((void**)&pXg,   g_Xg);

    // Grid for the fused kernel: ALL blocks must be co-resident (the workers
    // spin on the recurrence counter). Size from the occupancy query.
    int nper = 1;
    cudaOccupancyMaxActiveBlocksPerMultiprocessor(&nper, fused_rnn_logits, 256, SMEM_RNN);
    if (nper < 1) nper = 1;
    int nsm = 148;
    cudaDeviceGetAttribute(&nsm, cudaDevAttrMultiProcessorCount, 0);
    int fused_grid = nsm * nper;
    if (fused_grid < RNN_BLOCKS + 1) fused_grid = RNN_BLOCKS + 1;

    // 1. init: h0 fp16, c0, permuted bias, counters
    k_init<<<(BB * HH + 255) / 256, 256>>>(images, bih, bhh);

    // 2. embedding -> fp16
    k_embed<<<(BTR * 128 + 255) / 256, 256>>>(caps, Wemb);

    // 3. weight converts
    k_split_perm<<<(G4 * 128 + 255) / 256, 256>>>(Wih, pWih);
    k_split_perm<<<(G4 * 128 + 255) / 256, 256>>>(Whh, pWhh);
    k_split_out <<<(NPAD * 128 + 255) / 256, 256>>>(Wout);

    // 4. Xg = X @ Wih'^T + bias'   [3072 x 2048]
    {
        dim3 grid(G4 / 128, BTR / 128);
        mma_gemm<<<grid, 256, SMEM_DYN>>>(pX, pWih, pbias, pXg, G4);
    }

    // 5+6. fused: recurrence (32 blocks) + logits workers (rest), one launch
    fused_rnn_logits<<<fused_grid, 256, SMEM_RNN>>>(bout, out);

    // 7. t=0 one-hot rows + optional length tail
    {
        int extra = out_size - BB * OUTROW;
        if (extra < 0) extra = 0;
        k_start<<<(BB * VV + 255) / 256, 256>>>(out, clen, extra);
    }
}

// round 15
// speedup vs baseline: 3.3805x; 1.0144x over previous
#include <cuda_runtime.h>
#include <cuda_fp16.h>
#include <math.h>
#include <stdint.h>

#define BB   128
#define TT   24
#define EE   512
#define HH   512
#define VV   10000
#define G4   2048
#define BTR  3072
#define OUTROW 250000
#define NPAD 10112          // 79 * 128  (padded vocab rows)
#define RNN_BLOCKS 32
#define NSTART   16                      // output-init items
#define NXG      (TT * 16)               // 384 Xg tiles
#define NTILES_N 79
#define NLOG     (TT * NTILES_N)         // 1896 logits tiles
#define NT_TOT   (NSTART + NXG + NLOG)   // 2296

// ---------------- device scratch (no allocations allowed) ----------------
__device__ __half g_X   [BTR * EE];        // embedded captions (fp16)
__device__ __half g_Wih [G4 * EE];         // permuted W_ih (fp16)
__device__ __half g_Whh [G4 * HH];         // permuted W_hh (fp16)
__device__ __half g_Wout[NPAD * HH];       // padded W_out (fp16)
__device__ __half g_Hall[BTR * HH];        // all hidden states (fp16)
__device__ __half g_hA  [BB * HH];
__device__ __half g_hB  [BB * HH];
__device__ float  g_c   [BB * HH];
__device__ float  g_bias[G4];              // permuted b_ih+b_hh
__device__ float  g_Xg  [BTR * G4];        // input gates (permuted cols)
__device__ int    g_ctr;                   // recurrence step counter
__device__ int    g_tile;                  // global work queue
__device__ int    g_xg_done[TT];           // per-step Xg tile completion

// ---------------- small helpers ----------------
__device__ __forceinline__ float sigf(float x) { return 1.0f / (1.0f + expf(-x)); }

__device__ __forceinline__ uint32_t smem_to_u32(const void* p) {
    uint32_t a;
    asm("{ .reg .u64 t; cvta.to.shared.u64 t, %1; cvt.u32.u64 %0, t; }" : "=r"(a) : "l"(p));
    return a;
}

// ---------------- warp-level tensor ops (sm_80+ PTX; legal on plain sm_103) ----
__device__ __forceinline__ void ldsm_x4(uint32_t* r, uint32_t addr) {
    asm volatile("ldmatrix.sync.aligned.m8n8.x4.shared.b16 {%0,%1,%2,%3}, [%4];"
                 : "=r"(r[0]), "=r"(r[1]), "=r"(r[2]), "=r"(r[3]) : "r"(addr));
}

__device__ __forceinline__ void mma_f16(float* c, const uint32_t* a, const uint32_t* b) {
    asm volatile(
        "mma.sync.aligned.m16n8k16.row.col.f32.f16.f16.f32 "
        "{%0,%1,%2,%3}, {%4,%5,%6,%7}, {%8,%9}, {%0,%1,%2,%3};"
        : "+f"(c[0]), "+f"(c[1]), "+f"(c[2]), "+f"(c[3])
        : "r"(a[0]), "r"(a[1]), "r"(a[2]), "r"(a[3]), "r"(b[0]), "r"(b[1]));
}

// ---------------- cp.async (sm_80+ PTX) ----------------
__device__ __forceinline__ void cp_async16(uint32_t dst, const void* src) {
    asm volatile("cp.async.cg.shared.global [%0], [%1], 16;" :: "r"(dst), "l"(src));
}
#define CP_COMMIT() asm volatile("cp.async.commit_group;" ::: "memory")
// Last K-tile's data is the NEWEST committed group -> drain all; otherwise the
// next prefetch may remain in flight.
__device__ __forceinline__ void cp_wait(bool last) {
    if (last) asm volatile("cp.async.wait_group 0;" ::: "memory");
    else      asm volatile("cp.async.wait_group 1;" ::: "memory");
}

// ---------------- smem layout ----------------
// Plane = 128 rows x 64 fp16 k, rows padded to 144B (36 words; 36%32==4 =>
// ldmatrix phases conflict-free). Worker path: 3 stages of (A+B). RNN path:
// persistent Whh slice (64 x 512, rows padded to 1040B) + 3 h stages.
#define TILE_B   (128 * 144)
#define SM_A     0
#define SM_B     (1 * TILE_B)
#define STAGE_B  (2 * TILE_B)              // 36864
#define RW_ROW   1040
#define RSM_W    0                         // 64*1040 = 66560
#define RSM_H0   (64 * RW_ROW)
#define SMEM_FUSED (RSM_H0 + 3 * TILE_B)   // 121856 (>= 3*STAGE_B = 110592)

// Async-load one 128x64 fp16 tile (gmem ld = 512) into padded smem rows.
__device__ __forceinline__ void load_tile_async(uint32_t dst, const __half* src,
                                                int row0, int k0, int tid) {
#pragma unroll
    for (int i = 0; i < 4; i++) {
        int e  = tid + i * 256;           // 0..1023 groups of 8 fp16
        int r  = e >> 3;                  // 0..127
        int k8 = (e & 7) << 3;            // 0..56
        cp_async16(dst + r * 144 + k8 * 2,
                   src + (size_t)(row0 + r) * 512 + k0 + k8);
    }
}

__device__ __forceinline__ void load_stage(uint32_t stage,
        const __half* A, int arow0, const __half* Bm, int brow0,
        int k0, int tid) {
    load_tile_async(stage + SM_A, A, arow0, k0, tid);
    load_tile_async(stage + SM_B, Bm, brow0, k0, tid);
    CP_COMMIT();
}

// ---------------- GEMM mainloop: 3-stage pipeline, ONE sync per K-tile --------
// acc[mi][ni][4] += A[128xK] @ B[128xK]^T (fp16 in, fp32 acc). 8 warps =
// 2(m) x 4(n); warp tile 64m x 32n; K = 512 in 8 tiles of 64.
// At iteration kt the prefetch targets stage (kt+2)%3 == stage used at kt-1;
// the top-of-kt barrier guarantees all warps finished reading it.
__device__ __forceinline__ void gemm_mainloop(char* sm,
        const __half* A, int arow0, const __half* Bm, int brow0,
        float acc[4][4][4]) {
    const int tid  = threadIdx.x;
    const int lane = tid & 31;
    const int w    = tid >> 5;
    const int wm   = w & 1;
    const int wn   = w >> 1;
    const uint32_t sb = smem_to_u32(sm);

    const int lrow = lane & 15;
    const int lcol = (lane >> 4) * 16;

    load_stage(sb,           A, arow0, Bm, brow0, 0,  tid);
    load_stage(sb + STAGE_B, A, arow0, Bm, brow0, 64, tid);

    for (int kt = 0; kt < 8; kt++) {
        const uint32_t cur = sb + (kt % 3) * STAGE_B;
        cp_wait(kt == 7);
        __syncthreads();
        if (kt + 2 < 8)
            load_stage(sb + ((kt + 2) % 3) * STAGE_B,
                       A, arow0, Bm, brow0, (kt + 2) * 64, tid);

#pragma unroll
        for (int kc = 0; kc < 4; kc++) {
            uint32_t ah[4][4], bh[4][2];
#pragma unroll
            for (int mi = 0; mi < 4; mi++) {
                uint32_t a = cur + SM_A + (wm * 64 + mi * 16 + lrow) * 144 + kc * 32 + lcol;
                ldsm_x4(ah[mi], a);
            }
#pragma unroll
            for (int n2 = 0; n2 < 2; n2++) {
                uint32_t r0[4];
                uint32_t b = cur + SM_B + (wn * 32 + n2 * 16 + lrow) * 144 + kc * 32 + lcol;
                ldsm_x4(r0, b);
                bh[n2 * 2 + 0][0] = r0[0]; bh[n2 * 2 + 0][1] = r0[2];
                bh[n2 * 2 + 1][0] = r0[1]; bh[n2 * 2 + 1][1] = r0[3];
            }
#pragma unroll
            for (int mi = 0; mi < 4; mi++)
#pragma unroll
                for (int ni = 0; ni < 4; ni++)
                    mma_f16(acc[mi][ni], ah[mi], bh[ni]);
        }
    }
}

// ---------------- fused persistent kernel: EVERYTHING post-prep ----------------
// Blocks 0..31: LSTM recurrence (smem-resident Whh slice, 3-stage h pipeline,
//   per-step Xg gate + arrive on g_ctr).
// All blocks (workers immediately, rnn blocks afterwards) drain the queue:
//   [0,16):        output init (one-hot t=0 rows; item 0 also writes the tail)
//   [16,400):      Xg tiles, t-major; completion counted in g_xg_done[t]
//   [400,2296):    logits tiles, gated on g_ctr >= 32*(t+1)
__global__ __launch_bounds__(256, 1)
void fused_all(const float* __restrict__ bout, float* __restrict__ out,
               const int* __restrict__ clen, int extra) {
    extern __shared__ char sm[];
    const uint32_t sb = smem_to_u32(sm);
    const int tid  = threadIdx.x;
    const int lane = tid & 31;
    const int w    = tid >> 5;
    const int wm   = w & 1, wn = w >> 1;
    const int tpar = lane & 1;
    const int lrow = lane & 15;
    const int lcol = (lane >> 4) * 16;

    if (blockIdx.x < RNN_BLOCKS) {
        const int jb = blockIdx.x;

        // persistent Whh slice: 64 rows x 512 cols
#pragma unroll
        for (int i = 0; i < 16; i++) {
            int e  = tid + i * 256;
            int r  = e >> 6;
            int k8 = (e & 63) << 3;
            cp_async16(sb + RSM_W + r * RW_ROW + k8 * 2,
                       g_Whh + (size_t)(jb * 64 + r) * 512 + k8);
        }
        CP_COMMIT();

        for (int t = 0; t < TT; t++) {
            const __half* hin  = (t & 1) ? g_hB : g_hA;
            __half*       hout = (t & 1) ? g_hA : g_hB;

            load_tile_async(sb + RSM_H0,          hin, 0, 0,  tid); CP_COMMIT();
            load_tile_async(sb + RSM_H0 + TILE_B, hin, 0, 64, tid); CP_COMMIT();

            float acc[4][2][4];
#pragma unroll
            for (int a = 0; a < 4; a++)
#pragma unroll
                for (int b = 0; b < 2; b++)
#pragma unroll
                    for (int c = 0; c < 4; c++) acc[a][b][c] = 0.0f;

            for (int kt = 0; kt < 8; kt++) {
                const uint32_t curH = sb + RSM_H0 + (kt % 3) * TILE_B;
                cp_wait(kt == 7);
                __syncthreads();
                if (kt + 2 < 8) {
                    load_tile_async(sb + RSM_H0 + ((kt + 2) % 3) * TILE_B,
                                    hin, 0, (kt + 2) * 64, tid);
                    CP_COMMIT();
                }

#pragma unroll
                for (int kc = 0; kc < 4; kc++) {
                    uint32_t ah[4][4], bh[2][2];
#pragma unroll
                    for (int mi = 0; mi < 4; mi++) {
                        uint32_t a = curH + (wm * 64 + mi * 16 + lrow) * 144 + kc * 32 + lcol;
                        ldsm_x4(ah[mi], a);
                    }
                    {
                        uint32_t r0[4];
                        uint32_t b = sb + RSM_W + (wn * 16 + lrow) * RW_ROW
                                   + kt * 128 + kc * 32 + lcol;
                        ldsm_x4(r0, b);
                        bh[0][0] = r0[0]; bh[0][1] = r0[2];
                        bh[1][0] = r0[1]; bh[1][1] = r0[3];
                    }
#pragma unroll
                    for (int mi = 0; mi < 4; mi++)
#pragma unroll
                        for (int ni = 0; ni < 2; ni++)
                            mma_f16(acc[mi][ni], ah[mi], bh[ni]);
                }
            }

            // gate: all 16 Xg tiles of step t must be published
            if (tid == 0) {
                while (atomicAdd(&g_xg_done[t], 0) < 16) __nanosleep(32);
                __threadfence();
            }
            __syncthreads();

            // cell epilogue
#pragma unroll
            for (int mi = 0; mi < 4; mi++)
#pragma unroll
                for (int ni = 0; ni < 2; ni++) {
                    int m = wm * 64 + mi * 16 + (lane >> 2);
                    int n = jb * 64 + wn * 16 + ni * 8 + (lane & 3) * 2;
                    int r = t * 128 + m;
                    const float* xg = g_Xg + (size_t)r * G4;

                    float c0 = acc[mi][ni][0] + xg[n];
                    float c1 = acc[mi][ni][1] + xg[n + 1];
                    float c2 = acc[mi][ni][2] + xg[8 * G4 + n];
                    float c3 = acc[mi][ni][3] + xg[8 * G4 + n + 1];

                    float e0 = __shfl_xor_sync(0xFFFFFFFFu, c0, 1);
                    float e1 = __shfl_xor_sync(0xFFFFFFFFu, c1, 1);
                    float e2 = __shfl_xor_sync(0xFFFFFFFFu, c2, 1);
                    float e3 = __shfl_xor_sync(0xFFFFFFFFu, c3, 1);

                    int   row, j = n >> 2;
                    float iv, fv, gv, ov;
                    if (!tpar) { row = m;     iv = c0; fv = c1; gv = e0; ov = e1; }
                    else       { row = m + 8; iv = e2; fv = e3; gv = c2; ov = c3; }

                    float cO = g_c[row * HH + j];
                    float cN = sigf(fv) * cO + sigf(iv) * tanhf(gv);
                    float hN = sigf(ov) * tanhf(cN);
                    g_c[row * HH + j] = cN;

                    __half hh = __float2half(hN);
                    hout[row * HH + j] = hh;
                    g_Hall[(size_t)(t * 128 + row) * HH + j] = hh;
                }

            __threadfence();            // publish h + Hall (all threads)
            __syncthreads();
            if (tid == 0) {
                atomicAdd(&g_ctr, 1);
                if (t + 1 < TT) {
                    int target = RNN_BLOCKS * (t + 1);
                    while (atomicAdd(&g_ctr, 0) < target) { }
                }
            }
            __syncthreads();
        }
    }

    // ---------------- work-queue loop (all blocks) ----------------
    __shared__ int s_q;
    for (;;) {
        __syncthreads();
        if (tid == 0) s_q = atomicAdd(&g_tile, 1);
        __syncthreads();
        int q = s_q;
        if (q >= NT_TOT) break;

        if (q < NSTART) {
            // output init: 8 batch rows of the t=0 one-hot; item 0 also the tail
            int b0 = q * 8;
            for (int idx = tid; idx < 8 * VV; idx += 256) {
                int br = idx / VV, v = idx - br * VV;
                out[(size_t)(b0 + br) * OUTROW + v] = (v == 1) ? 1.0f : 0.0f;
            }
            if (q == 0)
                for (int idx = tid; idx < extra; idx += 256)
                    out[(size_t)BB * OUTROW + idx] =
                        (idx < BB) ? (float)(clen[idx] - 1) : 0.0f;
            continue;
        }

        if (q < NSTART + NXG) {
            // Xg tile: t-major so step-t tiles come off the queue first
            int idx = q - NSTART;
            int t = idx >> 4, nb = idx & 15;

            float acc[4][4][4];
#pragma unroll
            for (int a = 0; a < 4; a++)
#pragma unroll
                for (int b = 0; b < 4; b++)
#pragma unroll
                    for (int c = 0; c < 4; c++) acc[a][b][c] = 0.0f;

            gemm_mainloop(sm, g_X, t * 128, g_Wih, nb * 128, acc);

#pragma unroll
            for (int mi = 0; mi < 4; mi++)
#pragma unroll
                for (int ni = 0; ni < 4; ni++) {
                    int m = t * 128 + wm * 64 + mi * 16 + (lane >> 2);
                    int n = nb * 128 + wn * 32 + ni * 8 + (lane & 3) * 2;
                    g_Xg[(size_t)m * G4 + n]           = acc[mi][ni][0] + g_bias[n];
                    g_Xg[(size_t)m * G4 + n + 1]       = acc[mi][ni][1] + g_bias[n + 1];
                    g_Xg[(size_t)(m + 8) * G4 + n]     = acc[mi][ni][2] + g_bias[n];
                    g_Xg[(size_t)(m + 8) * G4 + n + 1] = acc[mi][ni][3] + g_bias[n + 1];
                }
            __threadfence();
            __syncthreads();
            if (tid == 0) atomicAdd(&g_xg_done[t], 1);
            continue;
        }

        // logits tile
        int idx = q - NSTART - NXG;
        int t  = idx / NTILES_N;
        int nb = idx - t * NTILES_N;

        if (tid == 0) {
            int target = RNN_BLOCKS * (t + 1);
            while (atomicAdd(&g_ctr, 0) < target) __nanosleep(64);
            __threadfence();
        }
        __syncthreads();

        float acc[4][4][4];
#pragma unroll
        for (int a = 0; a < 4; a++)
#pragma unroll
            for (int b = 0; b < 4; b++)
#pragma unroll
                for (int c = 0; c < 4; c++) acc[a][b][c] = 0.0f;

        gemm_mainloop(sm, g_Hall, t * 128, g_Wout, nb * 128, acc);

#pragma unroll
        for (int mi = 0; mi < 4; mi++)
#pragma unroll
            for (int ni = 0; ni < 4; ni++) {
                int b0 = wm * 64 + mi * 16 + (lane >> 2);
                int n  = nb * 128 + wn * 32 + ni * 8 + (lane & 3) * 2;
                float* d0 = out + (size_t)b0 * OUTROW + (size_t)(t + 1) * VV;
                float* d1 = out + (size_t)(b0 + 8) * OUTROW + (size_t)(t + 1) * VV;
                if (n < VV) {
                    d0[n] = acc[mi][ni][0] + bout[n];
                    d1[n] = acc[mi][ni][2] + bout[n];
                }
                if (n + 1 < VV) {
                    d0[n + 1] = acc[mi][ni][1] + bout[n + 1];
                    d1[n + 1] = acc[mi][ni][3] + bout[n + 1];
                }
            }
    }
}

// ---------------- merged prep kernel --------------------------------------
#define POFF1 (BB * HH)                    // 65536   hA / c
#define POFF2 (POFF1 + G4)                 // 67584   bias
#define POFF3 (POFF2 + BTR * 128)          // 460800  embed (float4 groups)
#define POFF4 (POFF3 + G4 * 128)           // 722944  Wih split
#define POFF5 (POFF4 + G4 * 128)           // 985088  Whh split
#define PTOT  (POFF5 + NPAD * 128)         // 2279424 Wout split

__global__ void k_prep(const float* __restrict__ img,
                       const float* __restrict__ bih, const float* __restrict__ bhh,
                       const int* __restrict__ caps, const float* __restrict__ Wemb,
                       const float* __restrict__ Wih, const float* __restrict__ Whh,
                       const float* __restrict__ Wout) {
    int i = blockIdx.x * blockDim.x + threadIdx.x;
    if (i == 0) {
        g_ctr = 0; g_tile = 0;
        for (int t = 0; t < TT; t++) g_xg_done[t] = 0;
    }
    if (i < POFF1) {
        g_hA[i] = __float2half(img[i]);
        g_c[i] = 0.0f;
        return;
    }
    if (i < POFF2) {                       // permuted bias: rp=j*4+g <- g*512+j
        int p = i - POFF1;
        int j = p >> 2, g = p & 3;
        g_bias[p] = bih[g * HH + j] + bhh[g * HH + j];
        return;
    }
    if (i < POFF3) {                       // embedding, float4 groups
        int p = i - POFF2;
        int e4 = p & 127, r = p >> 7;
        int t = r >> 7, b = r & 127;
        int tok = caps[b * TT + t];
        float4 v = make_float4(0.f, 0.f, 0.f, 0.f);
        if (tok != 0) v = *(const float4*)(Wemb + (size_t)tok * EE + e4 * 4);
        int base = r * EE + e4 * 4;
        g_X[base + 0] = __float2half(v.x);
        g_X[base + 1] = __float2half(v.y);
        g_X[base + 2] = __float2half(v.z);
        g_X[base + 3] = __float2half(v.w);
        return;
    }
    if (i < POFF5) {                       // Wih / Whh permuted split
        int p = (i < POFF4) ? (i - POFF3) : (i - POFF4);
        const float* W = (i < POFF4) ? Wih : Whh;
        __half* dst = (i < POFF4) ? g_Wih : g_Whh;
        int k4 = p & 127, rp = p >> 7;
        int j = rp >> 2, g = rp & 3;
        float4 v = *(const float4*)(W + (size_t)(g * HH + j) * 512 + k4 * 4);
        int base = rp * 512 + k4 * 4;
        dst[base + 0] = __float2half(v.x);
        dst[base + 1] = __float2half(v.y);
        dst[base + 2] = __float2half(v.z);
        dst[base + 3] = __float2half(v.w);
        return;
    }
    if (i < PTOT) {                        // Wout (zero-padded to NPAD rows)
        int p = i - POFF5;
        int k4 = p & 127, r = p >> 7;
        float4 v = make_float4(0.f, 0.f, 0.f, 0.f);
        if (r < VV) v = *(const float4*)(Wout + (size_t)r * HH + k4 * 4);
        int base = r * 512 + k4 * 4;
        g_Wout[base + 0] = __float2half(v.x);
        g_Wout[base + 1] = __float2half(v.y);
        g_Wout[base + 2] = __float2half(v.z);
        g_Wout[base + 3] = __float2half(v.w);
    }
}

// ---------------- launch ----------------
extern "C" void kernel_launch(void* const* d_in, const int* in_sizes, int n_in,
                              void* d_out, int out_size) {
    const float* images = (const float*)d_in[0];
    const int*   caps   = (const int*)  d_in[1];
    const int*   clen   = (const int*)  d_in[2];
    const float* Wemb   = (const float*)d_in[3];
    const float* Wih    = (const float*)d_in[4];
    const float* Whh    = (const float*)d_in[5];
    const float* bih    = (const float*)d_in[6];
    const float* bhh    = (const float*)d_in[7];
    const float* Wout   = (const float*)d_in[8];
    const float* bout   = (const float*)d_in[9];
    float* out = (float*)d_out;

    cudaFuncSetAttribute(fused_all, cudaFuncAttributeMaxDynamicSharedMemorySize, SMEM_FUSED);

    // Fused grid: all blocks must be co-resident (workers spin on counters).
    int nper = 1;
    cudaOccupancyMaxActiveBlocksPerMultiprocessor(&nper, fused_all, 256, SMEM_FUSED);
    if (nper < 1) nper = 1;
    int nsm = 148;
    cudaDeviceGetAttribute(&nsm, cudaDevAttrMultiProcessorCount, 0);
    int fused_grid = nsm * nper;
    if (fused_grid < RNN_BLOCKS + 1) fused_grid = RNN_BLOCKS + 1;

    int extra = out_size - BB * OUTROW;
    if (extra < 0) extra = 0;

    // 1. single merged prep launch
    k_prep<<<(PTOT + 255) / 256, 256>>>(images, bih, bhh, caps, Wemb, Wih, Whh, Wout);

    // 2. everything else: one persistent kernel
    fused_all<<<fused_grid, 256, SMEM_FUSED>>>(bout, out, clen, extra);
}

// round 16
// speedup vs baseline: 4.3708x; 1.2930x over previous
#include <cuda_runtime.h>
#include <cuda_fp16.h>
#include <math.h>
#include <stdint.h>

#define BB   128
#define TT   24
#define EE   512
#define HH   512
#define VV   10000
#define G4   2048
#define BTR  3072
#define OUTROW 250000
#define NPAD 10112          // 79 * 128  (padded vocab rows)
#define RNN_BLOCKS 32
#define NSTART   16                      // output-init items
#define NXG      (TT * 16)               // 384 Xg tiles
#define NTILES_N 79
#define NLOG     (TT * NTILES_N)         // 1896 logits tiles
#define NT_TOT   (NSTART + NXG + NLOG)   // 2296
#define NTHREADS 512

// ---------------- device scratch (no allocations allowed) ----------------
__device__ __half g_X   [BTR * EE];        // embedded captions (fp16)
__device__ __half g_Wih [G4 * EE];         // permuted W_ih (fp16)
__device__ __half g_Whh [G4 * HH];         // permuted W_hh (fp16)
__device__ __half g_Wout[NPAD * HH];       // padded W_out (fp16)
__device__ __half g_Hall[BTR * HH];        // all hidden states (fp16)
__device__ __half g_hA  [BB * HH];
__device__ __half g_hB  [BB * HH];
__device__ float  g_c   [BB * HH];
__device__ float  g_bias[G4];              // permuted b_ih+b_hh
__device__ float  g_Xg  [BTR * G4];        // input gates (permuted cols)
__device__ int    g_ctr;                   // recurrence step counter
__device__ int    g_tile;                  // global work queue
__device__ int    g_xg_done[TT];           // per-step Xg tile completion

// ---------------- small helpers ----------------
__device__ __forceinline__ float sigf(float x) { return 1.0f / (1.0f + expf(-x)); }

__device__ __forceinline__ uint32_t smem_to_u32(const void* p) {
    uint32_t a;
    asm("{ .reg .u64 t; cvta.to.shared.u64 t, %1; cvt.u32.u64 %0, t; }" : "=r"(a) : "l"(p));
    return a;
}

// ---------------- warp-level tensor ops (sm_80+ PTX; legal on plain sm_103) ----
__device__ __forceinline__ void ldsm_x4(uint32_t* r, uint32_t addr) {
    asm volatile("ldmatrix.sync.aligned.m8n8.x4.shared.b16 {%0,%1,%2,%3}, [%4];"
                 : "=r"(r[0]), "=r"(r[1]), "=r"(r[2]), "=r"(r[3]) : "r"(addr));
}

__device__ __forceinline__ void mma_f16(float* c, const uint32_t* a, const uint32_t* b) {
    asm volatile(
        "mma.sync.aligned.m16n8k16.row.col.f32.f16.f16.f32 "
        "{%0,%1,%2,%3}, {%4,%5,%6,%7}, {%8,%9}, {%0,%1,%2,%3};"
        : "+f"(c[0]), "+f"(c[1]), "+f"(c[2]), "+f"(c[3])
        : "r"(a[0]), "r"(a[1]), "r"(a[2]), "r"(a[3]), "r"(b[0]), "r"(b[1]));
}

// ---------------- cp.async (sm_80+ PTX) ----------------
__device__ __forceinline__ void cp_async16(uint32_t dst, const void* src) {
    asm volatile("cp.async.cg.shared.global [%0], [%1], 16;" :: "r"(dst), "l"(src));
}
#define CP_COMMIT() asm volatile("cp.async.commit_group;" ::: "memory")
// Last K-tile's data is the NEWEST committed group -> drain all; otherwise the
// next prefetch may remain in flight.
__device__ __forceinline__ void cp_wait(bool last) {
    if (last) asm volatile("cp.async.wait_group 0;" ::: "memory");
    else      asm volatile("cp.async.wait_group 1;" ::: "memory");
}

// ---------------- smem layout ----------------
// Plane = 128 rows x 64 fp16 k, rows padded to 144B (36 words; 36%32==4 =>
// ldmatrix phases conflict-free). Worker path: 3 stages of (A+B). RNN path:
// persistent Whh slice (64 x 512, rows padded to 1040B) + 3 h stages.
#define TILE_B   (128 * 144)
#define SM_A     0
#define SM_B     (1 * TILE_B)
#define STAGE_B  (2 * TILE_B)              // 36864
#define RW_ROW   1040
#define RSM_W    0                         // 64*1040 = 66560
#define RSM_H0   (64 * RW_ROW)
#define SMEM_FUSED (RSM_H0 + 3 * TILE_B)   // 121856 (>= 3*STAGE_B = 110592)

// Async-load one 128x64 fp16 tile (gmem ld = 512) into padded smem rows.
__device__ __forceinline__ void load_tile_async(uint32_t dst, const __half* src,
                                                int row0, int k0, int tid) {
#pragma unroll
    for (int i = 0; i < 2; i++) {
        int e  = tid + i * NTHREADS;      // 0..1023 groups of 8 fp16
        int r  = e >> 3;                  // 0..127
        int k8 = (e & 7) << 3;            // 0..56
        cp_async16(dst + r * 144 + k8 * 2,
                   src + (size_t)(row0 + r) * 512 + k0 + k8);
    }
}

__device__ __forceinline__ void load_stage(uint32_t stage,
        const __half* A, int arow0, const __half* Bm, int brow0,
        int k0, int tid) {
    load_tile_async(stage + SM_A, A, arow0, k0, tid);
    load_tile_async(stage + SM_B, Bm, brow0, k0, tid);
    CP_COMMIT();
}

// ---------------- GEMM mainloop: 3-stage pipeline, ONE sync per K-tile --------
// acc[mi][ni][4] += A[128xK] @ B[128xK]^T (fp16 in, fp32 acc). 16 warps =
// 4(m) x 4(n); warp tile 32m x 32n; K = 512 in 8 tiles of 64.
// At iteration kt the prefetch targets stage (kt+2)%3 == stage used at kt-1;
// the top-of-kt barrier guarantees all warps finished reading it.
__device__ __forceinline__ void gemm_mainloop(char* sm,
        const __half* A, int arow0, const __half* Bm, int brow0,
        float acc[2][4][4]) {
    const int tid  = threadIdx.x;
    const int lane = tid & 31;
    const int w    = tid >> 5;
    const int wm   = w & 3;
    const int wn   = w >> 2;
    const uint32_t sb = smem_to_u32(sm);

    const int lrow = lane & 15;
    const int lcol = (lane >> 4) * 16;

    load_stage(sb,           A, arow0, Bm, brow0, 0,  tid);
    load_stage(sb + STAGE_B, A, arow0, Bm, brow0, 64, tid);

    for (int kt = 0; kt < 8; kt++) {
        const uint32_t cur = sb + (kt % 3) * STAGE_B;
        cp_wait(kt == 7);
        __syncthreads();
        if (kt + 2 < 8)
            load_stage(sb + ((kt + 2) % 3) * STAGE_B,
                       A, arow0, Bm, brow0, (kt + 2) * 64, tid);

#pragma unroll
        for (int kc = 0; kc < 4; kc++) {
            uint32_t ah[2][4], bh[4][2];
#pragma unroll
            for (int mi = 0; mi < 2; mi++) {
                uint32_t a = cur + SM_A + (wm * 32 + mi * 16 + lrow) * 144 + kc * 32 + lcol;
                ldsm_x4(ah[mi], a);
            }
#pragma unroll
            for (int n2 = 0; n2 < 2; n2++) {
                uint32_t r0[4];
                uint32_t b = cur + SM_B + (wn * 32 + n2 * 16 + lrow) * 144 + kc * 32 + lcol;
                ldsm_x4(r0, b);
                bh[n2 * 2 + 0][0] = r0[0]; bh[n2 * 2 + 0][1] = r0[2];
                bh[n2 * 2 + 1][0] = r0[1]; bh[n2 * 2 + 1][1] = r0[3];
            }
#pragma unroll
            for (int mi = 0; mi < 2; mi++)
#pragma unroll
                for (int ni = 0; ni < 4; ni++)
                    mma_f16(acc[mi][ni], ah[mi], bh[ni]);
        }
    }
}

// ---------------- fused persistent kernel: EVERYTHING post-prep ----------------
// Blocks 0..31: LSTM recurrence (smem-resident Whh slice, 3-stage h pipeline,
//   per-step Xg gate + arrive on g_ctr). 16 warps = 4(m) x 4(n), warp 32m x 16n.
// All blocks (workers immediately, rnn blocks afterwards) drain the queue:
//   [0,16):        output init (one-hot t=0 rows; item 0 also writes the tail)
//   [16,400):      Xg tiles, t-major; completion counted in g_xg_done[t]
//   [400,2296):    logits tiles, gated on g_ctr >= 32*(t+1)
__global__ __launch_bounds__(NTHREADS, 1)
void fused_all(const float* __restrict__ bout, float* __restrict__ out,
               const int* __restrict__ clen, int extra) {
    extern __shared__ char sm[];
    const uint32_t sb = smem_to_u32(sm);
    const int tid  = threadIdx.x;
    const int lane = tid & 31;
    const int w    = tid >> 5;
    const int wm   = w & 3, wn = w >> 2;
    const int tpar = lane & 1;
    const int lrow = lane & 15;
    const int lcol = (lane >> 4) * 16;

    if (blockIdx.x < RNN_BLOCKS) {
        const int jb = blockIdx.x;

        // persistent Whh slice: 64 rows x 512 cols (4096 groups of 8)
#pragma unroll
        for (int i = 0; i < 8; i++) {
            int e  = tid + i * NTHREADS;
            int r  = e >> 6;
            int k8 = (e & 63) << 3;
            cp_async16(sb + RSM_W + r * RW_ROW + k8 * 2,
                       g_Whh + (size_t)(jb * 64 + r) * 512 + k8);
        }
        CP_COMMIT();

        for (int t = 0; t < TT; t++) {
            const __half* hin  = (t & 1) ? g_hB : g_hA;
            __half*       hout = (t & 1) ? g_hA : g_hB;

            load_tile_async(sb + RSM_H0,          hin, 0, 0,  tid); CP_COMMIT();
            load_tile_async(sb + RSM_H0 + TILE_B, hin, 0, 64, tid); CP_COMMIT();

            float acc[2][2][4];
#pragma unroll
            for (int a = 0; a < 2; a++)
#pragma unroll
                for (int b = 0; b < 2; b++)
#pragma unroll
                    for (int c = 0; c < 4; c++) acc[a][b][c] = 0.0f;

            for (int kt = 0; kt < 8; kt++) {
                const uint32_t curH = sb + RSM_H0 + (kt % 3) * TILE_B;
                cp_wait(kt == 7);
                __syncthreads();
                if (kt + 2 < 8) {
                    load_tile_async(sb + RSM_H0 + ((kt + 2) % 3) * TILE_B,
                                    hin, 0, (kt + 2) * 64, tid);
                    CP_COMMIT();
                }

#pragma unroll
                for (int kc = 0; kc < 4; kc++) {
                    uint32_t ah[2][4], bh[2][2];
#pragma unroll
                    for (int mi = 0; mi < 2; mi++) {
                        uint32_t a = curH + (wm * 32 + mi * 16 + lrow) * 144 + kc * 32 + lcol;
                        ldsm_x4(ah[mi], a);
                    }
                    {
                        uint32_t r0[4];
                        uint32_t b = sb + RSM_W + (wn * 16 + lrow) * RW_ROW
                                   + kt * 128 + kc * 32 + lcol;
                        ldsm_x4(r0, b);
                        bh[0][0] = r0[0]; bh[0][1] = r0[2];
                        bh[1][0] = r0[1]; bh[1][1] = r0[3];
                    }
#pragma unroll
                    for (int mi = 0; mi < 2; mi++)
#pragma unroll
                        for (int ni = 0; ni < 2; ni++)
                            mma_f16(acc[mi][ni], ah[mi], bh[ni]);
                }
            }

            // gate: all 16 Xg tiles of step t must be published
            if (tid == 0) {
                while (atomicAdd(&g_xg_done[t], 0) < 16) __nanosleep(32);
                __threadfence();
            }
            __syncthreads();

            // cell epilogue
#pragma unroll
            for (int mi = 0; mi < 2; mi++)
#pragma unroll
                for (int ni = 0; ni < 2; ni++) {
                    int m = wm * 32 + mi * 16 + (lane >> 2);
                    int n = jb * 64 + wn * 16 + ni * 8 + (lane & 3) * 2;
                    int r = t * 128 + m;
                    const float* xg = g_Xg + (size_t)r * G4;

                    float c0 = acc[mi][ni][0] + xg[n];
                    float c1 = acc[mi][ni][1] + xg[n + 1];
                    float c2 = acc[mi][ni][2] + xg[8 * G4 + n];
                    float c3 = acc[mi][ni][3] + xg[8 * G4 + n + 1];

                    float e0 = __shfl_xor_sync(0xFFFFFFFFu, c0, 1);
                    float e1 = __shfl_xor_sync(0xFFFFFFFFu, c1, 1);
                    float e2 = __shfl_xor_sync(0xFFFFFFFFu, c2, 1);
                    float e3 = __shfl_xor_sync(0xFFFFFFFFu, c3, 1);

                    int   row, j = n >> 2;
                    float iv, fv, gv, ov;
                    if (!tpar) { row = m;     iv = c0; fv = c1; gv = e0; ov = e1; }
                    else       { row = m + 8; iv = e2; fv = e3; gv = c2; ov = c3; }

                    float cO = g_c[row * HH + j];
                    float cN = sigf(fv) * cO + sigf(iv) * tanhf(gv);
                    float hN = sigf(ov) * tanhf(cN);
                    g_c[row * HH + j] = cN;

                    __half hh = __float2half(hN);
                    hout[row * HH + j] = hh;
                    g_Hall[(size_t)(t * 128 + row) * HH + j] = hh;
                }

            __threadfence();            // publish h + Hall (all threads)
            __syncthreads();
            if (tid == 0) {
                atomicAdd(&g_ctr, 1);
                if (t + 1 < TT) {
                    int target = RNN_BLOCKS * (t + 1);
                    while (atomicAdd(&g_ctr, 0) < target) { }
                }
            }
            __syncthreads();
        }
    }

    // ---------------- work-queue loop (all blocks) ----------------
    __shared__ int s_q;
    for (;;) {
        __syncthreads();
        if (tid == 0) s_q = atomicAdd(&g_tile, 1);
        __syncthreads();
        int q = s_q;
        if (q >= NT_TOT) break;

        if (q < NSTART) {
            // output init: 8 batch rows of the t=0 one-hot; item 0 also the tail
            int b0 = q * 8;
            for (int idx = tid; idx < 8 * VV; idx += NTHREADS) {
                int br = idx / VV, v = idx - br * VV;
                out[(size_t)(b0 + br) * OUTROW + v] = (v == 1) ? 1.0f : 0.0f;
            }
            if (q == 0)
                for (int idx = tid; idx < extra; idx += NTHREADS)
                    out[(size_t)BB * OUTROW + idx] =
                        (idx < BB) ? (float)(clen[idx] - 1) : 0.0f;
            continue;
        }

        if (q < NSTART + NXG) {
            // Xg tile: t-major so step-t tiles come off the queue first
            int idx = q - NSTART;
            int t = idx >> 4, nb = idx & 15;

            float acc[2][4][4];
#pragma unroll
            for (int a = 0; a < 2; a++)
#pragma unroll
                for (int b = 0; b < 4; b++)
#pragma unroll
                    for (int c = 0; c < 4; c++) acc[a][b][c] = 0.0f;

            gemm_mainloop(sm, g_X, t * 128, g_Wih, nb * 128, acc);

#pragma unroll
            for (int mi = 0; mi < 2; mi++)
#pragma unroll
                for (int ni = 0; ni < 4; ni++) {
                    int m = t * 128 + wm * 32 + mi * 16 + (lane >> 2);
                    int n = nb * 128 + wn * 32 + ni * 8 + (lane & 3) * 2;
                    g_Xg[(size_t)m * G4 + n]           = acc[mi][ni][0] + g_bias[n];
                    g_Xg[(size_t)m * G4 + n + 1]       = acc[mi][ni][1] + g_bias[n + 1];
                    g_Xg[(size_t)(m + 8) * G4 + n]     = acc[mi][ni][2] + g_bias[n];
                    g_Xg[(size_t)(m + 8) * G4 + n + 1] = acc[mi][ni][3] + g_bias[n + 1];
                }
            __threadfence();
            __syncthreads();
            if (tid == 0) atomicAdd(&g_xg_done[t], 1);
            continue;
        }

        // logits tile
        int idx = q - NSTART - NXG;
        int t  = idx / NTILES_N;
        int nb = idx - t * NTILES_N;

        if (tid == 0) {
            int target = RNN_BLOCKS * (t + 1);
            while (atomicAdd(&g_ctr, 0) < target) __nanosleep(64);
            __threadfence();
        }
        __syncthreads();

        float acc[2][4][4];
#pragma unroll
        for (int a = 0; a < 2; a++)
#pragma unroll
            for (int b = 0; b < 4; b++)
#pragma unroll
                for (int c = 0; c < 4; c++) acc[a][b][c] = 0.0f;

        gemm_mainloop(sm, g_Hall, t * 128, g_Wout, nb * 128, acc);

#pragma unroll
        for (int mi = 0; mi < 2; mi++)
#pragma unroll
            for (int ni = 0; ni < 4; ni++) {
                int b0 = wm * 32 + mi * 16 + (lane >> 2);
                int n  = nb * 128 + wn * 32 + ni * 8 + (lane & 3) * 2;
                float* d0 = out + (size_t)b0 * OUTROW + (size_t)(t + 1) * VV;
                float* d1 = out + (size_t)(b0 + 8) * OUTROW + (size_t)(t + 1) * VV;
                if (n < VV) {
                    d0[n] = acc[mi][ni][0] + bout[n];
                    d1[n] = acc[mi][ni][2] + bout[n];
                }
                if (n + 1 < VV) {
                    d0[n + 1] = acc[mi][ni][1] + bout[n + 1];
                    d1[n + 1] = acc[mi][ni][3] + bout[n + 1];
                }
            }
    }
}

// ---------------- merged prep kernel --------------------------------------
#define POFF1 (BB * HH)                    // 65536   hA / c
#define POFF2 (POFF1 + G4)                 // 67584   bias
#define POFF3 (POFF2 + BTR * 128)          // 460800  embed (float4 groups)
#define POFF4 (POFF3 + G4 * 128)           // 722944  Wih split
#define POFF5 (POFF4 + G4 * 128)           // 985088  Whh split
#define PTOT  (POFF5 + NPAD * 128)         // 2279424 Wout split

__global__ void k_prep(const float* __restrict__ img,
                       const float* __restrict__ bih, const float* __restrict__ bhh,
                       const int* __restrict__ caps, const float* __restrict__ Wemb,
                       const float* __restrict__ Wih, const float* __restrict__ Whh,
                       const float* __restrict__ Wout) {
    int i = blockIdx.x * blockDim.x + threadIdx.x;
    if (i == 0) {
        g_ctr = 0; g_tile = 0;
        for (int t = 0; t < TT; t++) g_xg_done[t] = 0;
    }
    if (i < POFF1) {
        g_hA[i] = __float2half(img[i]);
        g_c[i] = 0.0f;
        return;
    }
    if (i < POFF2) {                       // permuted bias: rp=j*4+g <- g*512+j
        int p = i - POFF1;
        int j = p >> 2, g = p & 3;
        g_bias[p] = bih[g * HH + j] + bhh[g * HH + j];
        return;
    }
    if (i < POFF3) {                       // embedding, float4 groups
        int p = i - POFF2;
        int e4 = p & 127, r = p >> 7;
        int t = r >> 7, b = r & 127;
        int tok = caps[b * TT + t];
        float4 v = make_float4(0.f, 0.f, 0.f, 0.f);
        if (tok != 0) v = *(const float4*)(Wemb + (size_t)tok * EE + e4 * 4);
        int base = r * EE + e4 * 4;
        g_X[base + 0] = __float2half(v.x);
        g_X[base + 1] = __float2half(v.y);
        g_X[base + 2] = __float2half(v.z);
        g_X[base + 3] = __float2half(v.w);
        return;
    }
    if (i < POFF5) {                       // Wih / Whh permuted split
        int p = (i < POFF4) ? (i - POFF3) : (i - POFF4);
        const float* W = (i < POFF4) ? Wih : Whh;
        __half* dst = (i < POFF4) ? g_Wih : g_Whh;
        int k4 = p & 127, rp = p >> 7;
        int j = rp >> 2, g = rp & 3;
        float4 v = *(const float4*)(W + (size_t)(g * HH + j) * 512 + k4 * 4);
        int base = rp * 512 + k4 * 4;
        dst[base + 0] = __float2half(v.x);
        dst[base + 1] = __float2half(v.y);
        dst[base + 2] = __float2half(v.z);
        dst[base + 3] = __float2half(v.w);
        return;
    }
    if (i < PTOT) {                        // Wout (zero-padded to NPAD rows)
        int p = i - POFF5;
        int k4 = p & 127, r = p >> 7;
        float4 v = make_float4(0.f, 0.f, 0.f, 0.f);
        if (r < VV) v = *(const float4*)(Wout + (size_t)r * HH + k4 * 4);
        int base = r * 512 + k4 * 4;
        g_Wout[base + 0] = __float2half(v.x);
        g_Wout[base + 1] = __float2half(v.y);
        g_Wout[base + 2] = __float2half(v.z);
        g_Wout[base + 3] = __float2half(v.w);
    }
}

// ---------------- launch ----------------
extern "C" void kernel_launch(void* const* d_in, const int* in_sizes, int n_in,
                              void* d_out, int out_size) {
    const float* images = (const float*)d_in[0];
    const int*   caps   = (const int*)  d_in[1];
    const int*   clen   = (const int*)  d_in[2];
    const float* Wemb   = (const float*)d_in[3];
    const float* Wih    = (const float*)d_in[4];
    const float* Whh    = (const float*)d_in[5];
    const float* bih    = (const float*)d_in[6];
    const float* bhh    = (const float*)d_in[7];
    const float* Wout   = (const float*)d_in[8];
    const float* bout   = (const float*)d_in[9];
    float* out = (float*)d_out;

    cudaFuncSetAttribute(fused_all, cudaFuncAttributeMaxDynamicSharedMemorySize, SMEM_FUSED);

    // Fused grid: all blocks must be co-resident (workers spin on counters).
    int nper = 1;
    cudaOccupancyMaxActiveBlocksPerMultiprocessor(&nper, fused_all, NTHREADS, SMEM_FUSED);
    if (nper < 1) nper = 1;
    int nsm = 148;
    cudaDeviceGetAttribute(&nsm, cudaDevAttrMultiProcessorCount, 0);
    int fused_grid = nsm * nper;
    if (fused_grid < RNN_BLOCKS + 1) fused_grid = RNN_BLOCKS + 1;

    int extra = out_size - BB * OUTROW;
    if (extra < 0) extra = 0;

    // 1. single merged prep launch
    k_prep<<<(PTOT + 255) / 256, 256>>>(images, bih, bhh, caps, Wemb, Wih, Whh, Wout);

    // 2. everything else: one persistent kernel
    fused_all<<<fused_grid, NTHREADS, SMEM_FUSED>>>(bout, out, clen, extra);
}